// round 1
// baseline (speedup 1.0000x reference)
#include <cuda_runtime.h>
#include <math.h>

#define Bb 4
#define Ss 2048
#define Dd 512
#define Hh 8
#define DK 64
#define BS (Bb*Ss)          // 8192 rows
#define LN_EPS 1e-5f
#define NEG_BIG (-1e30f)

// ---------------- scratch (static device globals; no allocation) ----------------
__device__ float g_xn[3][(size_t)BS*Dd];                 // normalized q,k,v   (50 MB)
__device__ float g_qkvh[3][(size_t)Bb*Hh*Ss*DK];         // head-major Q,K,V   (50 MB)
__device__ float g_x[(size_t)BS*Dd];                     // attention output   (16 MB)

// ---------------- Kernel 1: LayerNorm ----------------
__global__ void ln_kernel(const float* __restrict__ q, const float* __restrict__ k,
                          const float* __restrict__ v, const float* __restrict__ g,
                          const float* __restrict__ b) {
    int row = blockIdx.x;
    int which = blockIdx.y;
    const float* xs = which == 0 ? q : (which == 1 ? k : v);
    const float* x = xs + (size_t)row * Dd;
    float* y = g_xn[which] + (size_t)row * Dd;
    int t = threadIdx.x;

    float v0 = x[t], v1 = x[t + 256];
    float s = v0 + v1, s2 = v0 * v0 + v1 * v1;

    __shared__ float rs[8], rs2[8];
    #pragma unroll
    for (int o = 16; o; o >>= 1) {
        s  += __shfl_xor_sync(0xFFFFFFFFu, s,  o);
        s2 += __shfl_xor_sync(0xFFFFFFFFu, s2, o);
    }
    if ((t & 31) == 0) { rs[t >> 5] = s; rs2[t >> 5] = s2; }
    __syncthreads();
    __shared__ float smu, sinv;
    if (t == 0) {
        float S = 0.f, S2 = 0.f;
        #pragma unroll
        for (int i = 0; i < 8; i++) { S += rs[i]; S2 += rs2[i]; }
        float mu = S * (1.f / 512.f);
        float var = S2 * (1.f / 512.f) - mu * mu;
        smu = mu; sinv = rsqrtf(var + LN_EPS);
    }
    __syncthreads();
    float mu = smu, inv = sinv;
    y[t]       = (v0 - mu) * inv * g[t]       + b[t];
    y[t + 256] = (v1 - mu) * inv * g[t + 256] + b[t + 256];
}

// ---------------- Kernel 2: QKV projection GEMM (head-major epilogue) ----------------
// C[8192,512] = XN @ W + bias ; write out[b][h][s][d]
__global__ void __launch_bounds__(256) qkv_proj_kernel(
    const float* __restrict__ wq, const float* __restrict__ wk, const float* __restrict__ wv,
    const float* __restrict__ bq, const float* __restrict__ bk, const float* __restrict__ bv) {
    const int BM = 64, BN = 64, BK = 16;
    __shared__ float sA[BK][BM + 4];   // sA[k][m]
    __shared__ float sB[BK][BN + 4];   // sB[k][n]

    int z = blockIdx.z;
    const float* A = g_xn[z];
    const float* W = z == 0 ? wq : (z == 1 ? wk : wv);
    const float* bias = z == 0 ? bq : (z == 1 ? bk : bv);
    float* out = g_qkvh[z];

    int tid = threadIdx.x;
    int tx = tid & 15, ty = tid >> 4;
    int m0 = blockIdx.x * BM, n0 = blockIdx.y * BN;

    float acc[4][4] = {};

    for (int k0 = 0; k0 < Dd; k0 += BK) {
        #pragma unroll
        for (int i = 0; i < 4; i++) {
            int idx = tid + i * 256;                 // 1024 = 64m x 16k
            int kk = idx & 15, m = idx >> 4;
            sA[kk][m] = A[(size_t)(m0 + m) * Dd + k0 + kk];
        }
        #pragma unroll
        for (int i = 0; i < 4; i++) {
            int idx = tid + i * 256;                 // 1024 = 16k x 64n
            int n = idx & 63, kk = idx >> 6;
            sB[kk][n] = W[(size_t)(k0 + kk) * Dd + n0 + n];
        }
        __syncthreads();
        #pragma unroll
        for (int kk = 0; kk < BK; kk++) {
            float4 av = *(float4*)&sA[kk][ty * 4];
            float4 bvv = *(float4*)&sB[kk][tx * 4];
            float a[4] = {av.x, av.y, av.z, av.w};
            float bb[4] = {bvv.x, bvv.y, bvv.z, bvv.w};
            #pragma unroll
            for (int i = 0; i < 4; i++)
                #pragma unroll
                for (int j = 0; j < 4; j++)
                    acc[i][j] = fmaf(a[i], bb[j], acc[i][j]);
        }
        __syncthreads();
    }

    int n = n0 + tx * 4;
    int hh = n >> 6, dd = n & 63;
    float b0 = bias[n], b1 = bias[n + 1], b2 = bias[n + 2], b3 = bias[n + 3];
    #pragma unroll
    for (int i = 0; i < 4; i++) {
        int m = m0 + ty * 4 + i;
        int bidx = m >> 11, srow = m & 2047;
        float4 r;
        r.x = acc[i][0] + b0; r.y = acc[i][1] + b1;
        r.z = acc[i][2] + b2; r.w = acc[i][3] + b3;
        *(float4*)&out[(((size_t)(bidx * Hh + hh) * Ss + srow) * DK) + dd] = r;
    }
}

// ---------------- Kernel 3: attention (scores strip in smem, single pass) ----------------
#define TQ 16
#define TK 128
#define VPAD 68        // 64 + 4 pad (row stride for K/V tiles)
#define SMEM_FLOATS (TQ*Ss + TK*VPAD + TQ*DK)

__global__ void __launch_bounds__(256, 1) attn_kernel(
    const float* __restrict__ pos, const int* __restrict__ mask, float* __restrict__ d_out) {
    extern __shared__ float smem[];
    float* sS = smem;                      // [TQ][2048]
    float* sU = smem + TQ * Ss;            // [128][VPAD]   (K tile, then V tile)
    float* sQ = sU + TK * VPAD;            // [16][64]

    int qt = blockIdx.x, h = blockIdx.y, b = blockIdx.z;
    const float* Q = g_qkvh[0] + (size_t)(b * Hh + h) * Ss * DK;
    const float* K = g_qkvh[1] + (size_t)(b * Hh + h) * Ss * DK;
    const float* V = g_qkvh[2] + (size_t)(b * Hh + h) * Ss * DK;
    float* attn_out = d_out + (size_t)BS * Dd
                    + ((size_t)((b * Hh + h) * Ss) + (size_t)qt * TQ) * Ss;

    int tid = threadIdx.x;

    // load Q tile: 16x64 = 256 float4
    {
        int r = tid >> 4, c4 = tid & 15;
        float4 qv = *(const float4*)&Q[(size_t)(qt * TQ + r) * DK + c4 * 4];
        *(float4*)&sQ[r * DK + c4 * 4] = qv;
    }

    const int kg = tid & 31;    // 4 keys: kg*4..kg*4+3
    const int qg = tid >> 5;    // 2 rows: qg*2, qg*2+1
    const float scale = 0.125f; // 1/sqrt(64)

    // ---- scores: QK^T * scale + pos, masked -> sS ----
    for (int kt = 0; kt < Ss / TK; kt++) {
        int kbase = kt * TK;
        __syncthreads();
        #pragma unroll
        for (int i = 0; i < 8; i++) {
            int idx = tid + i * 256;                  // 2048 float4 = 128key x 16d4
            int d4 = idx & 15, key = idx >> 4;
            float4 kv = *(const float4*)&K[(size_t)(kbase + key) * DK + d4 * 4];
            *(float4*)&sU[key * VPAD + d4 * 4] = kv;
        }
        __syncthreads();

        float acc[2][4] = {};
        const float* q0p = &sQ[(qg * 2) * DK];
        const float* q1p = q0p + DK;
        const float* k0p = &sU[(kg * 4 + 0) * VPAD];
        const float* k1p = &sU[(kg * 4 + 1) * VPAD];
        const float* k2p = &sU[(kg * 4 + 2) * VPAD];
        const float* k3p = &sU[(kg * 4 + 3) * VPAD];
        #pragma unroll
        for (int d4 = 0; d4 < 16; d4++) {
            float4 q0 = *(const float4*)&q0p[d4 * 4];
            float4 q1 = *(const float4*)&q1p[d4 * 4];
            float4 kv0 = *(const float4*)&k0p[d4 * 4];
            float4 kv1 = *(const float4*)&k1p[d4 * 4];
            float4 kv2 = *(const float4*)&k2p[d4 * 4];
            float4 kv3 = *(const float4*)&k3p[d4 * 4];
            acc[0][0] = fmaf(q0.x,kv0.x,fmaf(q0.y,kv0.y,fmaf(q0.z,kv0.z,fmaf(q0.w,kv0.w,acc[0][0]))));
            acc[0][1] = fmaf(q0.x,kv1.x,fmaf(q0.y,kv1.y,fmaf(q0.z,kv1.z,fmaf(q0.w,kv1.w,acc[0][1]))));
            acc[0][2] = fmaf(q0.x,kv2.x,fmaf(q0.y,kv2.y,fmaf(q0.z,kv2.z,fmaf(q0.w,kv2.w,acc[0][2]))));
            acc[0][3] = fmaf(q0.x,kv3.x,fmaf(q0.y,kv3.y,fmaf(q0.z,kv3.z,fmaf(q0.w,kv3.w,acc[0][3]))));
            acc[1][0] = fmaf(q1.x,kv0.x,fmaf(q1.y,kv0.y,fmaf(q1.z,kv0.z,fmaf(q1.w,kv0.w,acc[1][0]))));
            acc[1][1] = fmaf(q1.x,kv1.x,fmaf(q1.y,kv1.y,fmaf(q1.z,kv1.z,fmaf(q1.w,kv1.w,acc[1][1]))));
            acc[1][2] = fmaf(q1.x,kv2.x,fmaf(q1.y,kv2.y,fmaf(q1.z,kv2.z,fmaf(q1.w,kv2.w,acc[1][2]))));
            acc[1][3] = fmaf(q1.x,kv3.x,fmaf(q1.y,kv3.y,fmaf(q1.z,kv3.z,fmaf(q1.w,kv3.w,acc[1][3]))));
        }

        #pragma unroll
        for (int r = 0; r < 2; r++) {
            int lq = qg * 2 + r;
            int qrow = qt * TQ + lq;
            float4 pv = *(const float4*)&pos[(size_t)qrow * Ss + kbase + kg * 4];
            int4   mv = *(const int4*)&mask[(size_t)qrow * Ss + kbase + kg * 4];
            float4 sv;
            sv.x = mv.x ? fmaf(acc[r][0], scale, pv.x) : NEG_BIG;
            sv.y = mv.y ? fmaf(acc[r][1], scale, pv.y) : NEG_BIG;
            sv.z = mv.z ? fmaf(acc[r][2], scale, pv.z) : NEG_BIG;
            sv.w = mv.w ? fmaf(acc[r][3], scale, pv.w) : NEG_BIG;
            *(float4*)&sS[lq * Ss + kbase + kg * 4] = sv;
        }
    }
    __syncthreads();

    // ---- softmax per row (8 warps x 2 rows), write attn to gmem ----
    {
        int w = tid >> 5, l = tid & 31;
        #pragma unroll
        for (int r2 = 0; r2 < 2; r2++) {
            int r = w * 2 + r2;
            float4* row = (float4*)&sS[r * Ss];
            float m = NEG_BIG;
            for (int c = l; c < Ss / 4; c += 32) {
                float4 vv = row[c];
                m = fmaxf(m, fmaxf(fmaxf(vv.x, vv.y), fmaxf(vv.z, vv.w)));
            }
            #pragma unroll
            for (int o = 16; o; o >>= 1) m = fmaxf(m, __shfl_xor_sync(0xFFFFFFFFu, m, o));
            float sum = 0.f;
            for (int c = l; c < Ss / 4; c += 32) {
                float4 vv = row[c];
                vv.x = __expf(vv.x - m); vv.y = __expf(vv.y - m);
                vv.z = __expf(vv.z - m); vv.w = __expf(vv.w - m);
                row[c] = vv;
                sum += vv.x + vv.y + vv.z + vv.w;
            }
            #pragma unroll
            for (int o = 16; o; o >>= 1) sum += __shfl_xor_sync(0xFFFFFFFFu, sum, o);
            float inv = 1.f / sum;
            float4* arow = (float4*)&attn_out[(size_t)r * Ss];
            for (int c = l; c < Ss / 4; c += 32) {
                float4 vv = row[c];
                vv.x *= inv; vv.y *= inv; vv.z *= inv; vv.w *= inv;
                row[c] = vv;
                arow[c] = vv;
            }
        }
    }

    // ---- PV: out[16][64] = attn[16][2048] @ V[2048][64] ----
    {
        int qi = tid >> 4;     // 0..15
        int dg = tid & 15;     // 0..15 (4 d each)
        float4 oacc = make_float4(0.f, 0.f, 0.f, 0.f);
        for (int kt = 0; kt < Ss / TK; kt++) {
            __syncthreads();   // (first iter: softmax done; later: prev V consumers done)
            #pragma unroll
            for (int i = 0; i < 8; i++) {
                int idx = tid + i * 256;
                int d4 = idx & 15, key = idx >> 4;
                float4 vv = *(const float4*)&V[(size_t)(kt * TK + key) * DK + d4 * 4];
                *(float4*)&sU[key * VPAD + d4 * 4] = vv;
            }
            __syncthreads();
            const float* prow = &sS[qi * Ss + kt * TK];
            #pragma unroll 4
            for (int k4 = 0; k4 < TK / 4; k4++) {
                float4 p = *(const float4*)&prow[k4 * 4];
                float4 v0 = *(const float4*)&sU[(k4 * 4 + 0) * VPAD + dg * 4];
                float4 v1 = *(const float4*)&sU[(k4 * 4 + 1) * VPAD + dg * 4];
                float4 v2 = *(const float4*)&sU[(k4 * 4 + 2) * VPAD + dg * 4];
                float4 v3 = *(const float4*)&sU[(k4 * 4 + 3) * VPAD + dg * 4];
                oacc.x = fmaf(p.x, v0.x, fmaf(p.y, v1.x, fmaf(p.z, v2.x, fmaf(p.w, v3.x, oacc.x))));
                oacc.y = fmaf(p.x, v0.y, fmaf(p.y, v1.y, fmaf(p.z, v2.y, fmaf(p.w, v3.y, oacc.y))));
                oacc.z = fmaf(p.x, v0.z, fmaf(p.y, v1.z, fmaf(p.z, v2.z, fmaf(p.w, v3.z, oacc.z))));
                oacc.w = fmaf(p.x, v0.w, fmaf(p.y, v1.w, fmaf(p.z, v2.w, fmaf(p.w, v3.w, oacc.w))));
            }
        }
        int srow = qt * TQ + qi;
        *(float4*)&g_x[((size_t)(b * Ss + srow)) * Dd + h * DK + dg * 4] = oacc;
    }
}

// ---------------- Kernel 4: output projection ----------------
__global__ void __launch_bounds__(256) out_proj_kernel(
    const float* __restrict__ W, const float* __restrict__ bias,
    const float* __restrict__ ls, float* __restrict__ Cout) {
    const int BM = 64, BN = 64, BK = 16;
    __shared__ float sA[BK][BM + 4];
    __shared__ float sB[BK][BN + 4];

    int tid = threadIdx.x;
    int tx = tid & 15, ty = tid >> 4;
    int m0 = blockIdx.x * BM, n0 = blockIdx.y * BN;

    float acc[4][4] = {};
    for (int k0 = 0; k0 < Dd; k0 += BK) {
        #pragma unroll
        for (int i = 0; i < 4; i++) {
            int idx = tid + i * 256;
            int kk = idx & 15, m = idx >> 4;
            sA[kk][m] = g_x[(size_t)(m0 + m) * Dd + k0 + kk];
        }
        #pragma unroll
        for (int i = 0; i < 4; i++) {
            int idx = tid + i * 256;
            int n = idx & 63, kk = idx >> 6;
            sB[kk][n] = W[(size_t)(k0 + kk) * Dd + n0 + n];
        }
        __syncthreads();
        #pragma unroll
        for (int kk = 0; kk < BK; kk++) {
            float4 av = *(float4*)&sA[kk][ty * 4];
            float4 bvv = *(float4*)&sB[kk][tx * 4];
            float a[4] = {av.x, av.y, av.z, av.w};
            float bb[4] = {bvv.x, bvv.y, bvv.z, bvv.w};
            #pragma unroll
            for (int i = 0; i < 4; i++)
                #pragma unroll
                for (int j = 0; j < 4; j++)
                    acc[i][j] = fmaf(a[i], bb[j], acc[i][j]);
        }
        __syncthreads();
    }

    int n = n0 + tx * 4;
    float b0 = bias[n], b1 = bias[n+1], b2 = bias[n+2], b3 = bias[n+3];
    float l0 = ls[n], l1 = ls[n+1], l2 = ls[n+2], l3 = ls[n+3];
    #pragma unroll
    for (int i = 0; i < 4; i++) {
        int m = m0 + ty * 4 + i;
        float4 r;
        r.x = (acc[i][0] + b0) * l0;
        r.y = (acc[i][1] + b1) * l1;
        r.z = (acc[i][2] + b2) * l2;
        r.w = (acc[i][3] + b3) * l3;
        *(float4*)&Cout[(size_t)m * Dd + n] = r;
    }
}

// ---------------- launch ----------------
extern "C" void kernel_launch(void* const* d_in, const int* in_sizes, int n_in,
                              void* d_out, int out_size) {
    const float* q    = (const float*)d_in[0];
    const float* k    = (const float*)d_in[1];
    const float* v    = (const float*)d_in[2];
    const int*   mask = (const int*)  d_in[3];
    const float* pos  = (const float*)d_in[4];
    const float* ln_g = (const float*)d_in[5];
    const float* ln_b = (const float*)d_in[6];
    const float* wq   = (const float*)d_in[7];
    const float* bq   = (const float*)d_in[8];
    const float* wk   = (const float*)d_in[9];
    const float* bk   = (const float*)d_in[10];
    const float* wv   = (const float*)d_in[11];
    const float* bv   = (const float*)d_in[12];
    const float* wo   = (const float*)d_in[13];
    const float* bo   = (const float*)d_in[14];
    const float* ls   = (const float*)d_in[15];
    float* out = (float*)d_out;

    size_t smem_bytes = (size_t)SMEM_FLOATS * sizeof(float);   // 169,984 B
    cudaFuncSetAttribute(attn_kernel, cudaFuncAttributeMaxDynamicSharedMemorySize,
                         (int)smem_bytes);

    ln_kernel<<<dim3(BS, 3), 256>>>(q, k, v, ln_g, ln_b);
    qkv_proj_kernel<<<dim3(BS / 64, Dd / 64, 3), 256>>>(wq, wk, wv, bq, bk, bv);
    attn_kernel<<<dim3(Ss / TQ, Hh, Bb), 256, smem_bytes>>>(pos, mask, out);
    out_proj_kernel<<<dim3(BS / 64, Dd / 64), 256>>>(wo, bo, ls, out);
}

// round 2
// speedup vs baseline: 2.2012x; 2.2012x over previous
#include <cuda_runtime.h>
#include <math.h>
#include <stdint.h>

#define Bb 4
#define Ss 2048
#define Dd 512
#define Hh 8
#define DK 64
#define BS (Bb*Ss)          // 8192 rows
#define LN_EPS 1e-5f
#define NEG_BIG (-1e30f)

// ---------------- scratch (static device globals; no allocation) ----------------
__device__ float g_xn[3][(size_t)BS*Dd];                 // normalized q,k,v   (50 MB)
__device__ float g_qkvh[3][(size_t)Bb*Hh*Ss*DK];         // head-major Q,K,V   (50 MB)
__device__ float g_x[(size_t)BS*Dd];                     // attention output   (16 MB)

// ---------------- tf32 mma helpers ----------------
__device__ __forceinline__ uint32_t f2tf32(float x) {
    uint32_t r;
    asm volatile("cvt.rna.tf32.f32 %0, %1;" : "=r"(r) : "f"(x));
    return r;
}

__device__ __forceinline__ void mma_tf32(float4& d, const uint32_t a[4],
                                         uint32_t b0, uint32_t b1) {
    asm volatile(
        "mma.sync.aligned.m16n8k8.row.col.f32.tf32.tf32.f32 "
        "{%0,%1,%2,%3}, {%4,%5,%6,%7}, {%8,%9}, {%0,%1,%2,%3};\n"
        : "+f"(d.x), "+f"(d.y), "+f"(d.z), "+f"(d.w)
        : "r"(a[0]), "r"(a[1]), "r"(a[2]), "r"(a[3]), "r"(b0), "r"(b1));
}

// ---------------- Kernel 1: LayerNorm ----------------
__global__ void ln_kernel(const float* __restrict__ q, const float* __restrict__ k,
                          const float* __restrict__ v, const float* __restrict__ g,
                          const float* __restrict__ b) {
    int row = blockIdx.x;
    int which = blockIdx.y;
    const float* xs = which == 0 ? q : (which == 1 ? k : v);
    const float* x = xs + (size_t)row * Dd;
    float* y = g_xn[which] + (size_t)row * Dd;
    int t = threadIdx.x;

    float v0 = x[t], v1 = x[t + 256];
    float s = v0 + v1, s2 = v0 * v0 + v1 * v1;

    __shared__ float rs[8], rs2[8];
    #pragma unroll
    for (int o = 16; o; o >>= 1) {
        s  += __shfl_xor_sync(0xFFFFFFFFu, s,  o);
        s2 += __shfl_xor_sync(0xFFFFFFFFu, s2, o);
    }
    if ((t & 31) == 0) { rs[t >> 5] = s; rs2[t >> 5] = s2; }
    __syncthreads();
    __shared__ float smu, sinv;
    if (t == 0) {
        float S = 0.f, S2 = 0.f;
        #pragma unroll
        for (int i = 0; i < 8; i++) { S += rs[i]; S2 += rs2[i]; }
        float mu = S * (1.f / 512.f);
        float var = S2 * (1.f / 512.f) - mu * mu;
        smu = mu; sinv = rsqrtf(var + LN_EPS);
    }
    __syncthreads();
    float mu = smu, inv = sinv;
    y[t]       = (v0 - mu) * inv * g[t]       + b[t];
    y[t + 256] = (v1 - mu) * inv * g[t + 256] + b[t + 256];
}

// ---------------- Kernel 2: QKV projection GEMM (head-major epilogue) ----------------
__global__ void __launch_bounds__(256) qkv_proj_kernel(
    const float* __restrict__ wq, const float* __restrict__ wk, const float* __restrict__ wv,
    const float* __restrict__ bq, const float* __restrict__ bk, const float* __restrict__ bv) {
    const int BM = 64, BN = 64, BK = 16;
    __shared__ float sA[BK][BM + 4];   // sA[k][m]
    __shared__ float sB[BK][BN + 4];   // sB[k][n]

    int z = blockIdx.z;
    const float* A = g_xn[z];
    const float* W = z == 0 ? wq : (z == 1 ? wk : wv);
    const float* bias = z == 0 ? bq : (z == 1 ? bk : bv);
    float* out = g_qkvh[z];

    int tid = threadIdx.x;
    int tx = tid & 15, ty = tid >> 4;
    int m0 = blockIdx.x * BM, n0 = blockIdx.y * BN;

    float acc[4][4] = {};

    for (int k0 = 0; k0 < Dd; k0 += BK) {
        #pragma unroll
        for (int i = 0; i < 4; i++) {
            int idx = tid + i * 256;
            int kk = idx & 15, m = idx >> 4;
            sA[kk][m] = A[(size_t)(m0 + m) * Dd + k0 + kk];
        }
        #pragma unroll
        for (int i = 0; i < 4; i++) {
            int idx = tid + i * 256;
            int n = idx & 63, kk = idx >> 6;
            sB[kk][n] = W[(size_t)(k0 + kk) * Dd + n0 + n];
        }
        __syncthreads();
        #pragma unroll
        for (int kk = 0; kk < BK; kk++) {
            float4 av = *(float4*)&sA[kk][ty * 4];
            float4 bvv = *(float4*)&sB[kk][tx * 4];
            float a[4] = {av.x, av.y, av.z, av.w};
            float bb[4] = {bvv.x, bvv.y, bvv.z, bvv.w};
            #pragma unroll
            for (int i = 0; i < 4; i++)
                #pragma unroll
                for (int j = 0; j < 4; j++)
                    acc[i][j] = fmaf(a[i], bb[j], acc[i][j]);
        }
        __syncthreads();
    }

    int n = n0 + tx * 4;
    int hh = n >> 6, dd = n & 63;
    float b0 = bias[n], b1 = bias[n + 1], b2 = bias[n + 2], b3 = bias[n + 3];
    #pragma unroll
    for (int i = 0; i < 4; i++) {
        int m = m0 + ty * 4 + i;
        int bidx = m >> 11, srow = m & 2047;
        float4 r;
        r.x = acc[i][0] + b0; r.y = acc[i][1] + b1;
        r.z = acc[i][2] + b2; r.w = acc[i][3] + b3;
        *(float4*)&out[(((size_t)(bidx * Hh + hh) * Ss + srow) * DK) + dd] = r;
    }
}

// ---------------- Kernel 3: attention (tf32 tensor cores, score strip in smem) ----------------
#define TQ 16
#define TK 128
#define VPAD 68          // K/V tile row stride (conflict-free)
#define SPAD 2056        // score strip row stride (2048 + 8)
#define SMEM_FLOATS (TQ*SPAD + TK*VPAD + TQ*DK)

__global__ void __launch_bounds__(256, 1) attn_kernel(
    const float* __restrict__ pos, const int* __restrict__ mask, float* __restrict__ d_out) {
    extern __shared__ float smem[];
    float* sS = smem;                      // [16][SPAD]
    float* sU = smem + TQ * SPAD;          // [128][VPAD]   (K tile, then V tile)
    float* sQ = sU + TK * VPAD;            // [16][64]

    int qt = blockIdx.x, h = blockIdx.y, b = blockIdx.z;
    const float* Q = g_qkvh[0] + (size_t)(b * Hh + h) * Ss * DK;
    const float* K = g_qkvh[1] + (size_t)(b * Hh + h) * Ss * DK;
    const float* V = g_qkvh[2] + (size_t)(b * Hh + h) * Ss * DK;
    float* attn_out = d_out + (size_t)BS * Dd
                    + ((size_t)((b * Hh + h) * Ss) + (size_t)qt * TQ) * Ss;

    int tid = threadIdx.x;
    int lane = tid & 31, w = tid >> 5;
    int g = lane >> 2;        // fragment row group 0..7
    int t = lane & 3;         // fragment k/col id 0..3

    // load Q tile: 16x64 = 256 float4
    {
        int r = tid >> 4, c4 = tid & 15;
        *(float4*)&sQ[r * DK + c4 * 4] =
            *(const float4*)&Q[(size_t)(qt * TQ + r) * DK + c4 * 4];
    }
    __syncthreads();

    // Q fragments held in registers for the whole kernel (A of m16n8k8, 8 k-steps)
    uint32_t qa[8][4];
    #pragma unroll
    for (int ks = 0; ks < 8; ks++) {
        int k0 = ks * 8;
        qa[ks][0] = f2tf32(sQ[g * DK + k0 + t]);
        qa[ks][1] = f2tf32(sQ[(g + 8) * DK + k0 + t]);
        qa[ks][2] = f2tf32(sQ[g * DK + k0 + t + 4]);
        qa[ks][3] = f2tf32(sQ[(g + 8) * DK + k0 + t + 4]);
    }

    const float scale = 0.125f; // 1/sqrt(64)

    // ---- scores: QK^T * scale + pos, masked -> sS ----
    for (int kt = 0; kt < Ss / TK; kt++) {
        int kbase = kt * TK;
        #pragma unroll
        for (int i = 0; i < 8; i++) {
            int idx = tid + i * 256;                  // 2048 float4 = 128key x 16d4
            int d4 = idx & 15, key = idx >> 4;
            *(float4*)&sU[key * VPAD + d4 * 4] =
                *(const float4*)&K[(size_t)(kbase + key) * DK + d4 * 4];
        }
        __syncthreads();

        #pragma unroll
        for (int nt = 0; nt < 2; nt++) {
            int n0 = w * 16 + nt * 8;                 // key offset within tile
            float4 acc = make_float4(0.f, 0.f, 0.f, 0.f);
            #pragma unroll
            for (int ks = 0; ks < 8; ks++) {
                const float* kp = &sU[(n0 + g) * VPAD + ks * 8 + t];
                uint32_t b0 = f2tf32(kp[0]);
                uint32_t b1 = f2tf32(kp[4]);
                mma_tf32(acc, qa[ks], b0, b1);
            }
            // epilogue: scale + pos bias + mask, scatter into score strip
            int c0 = n0 + 2 * t;
            int gk = kbase + c0;                      // global key col (even)
            int q0 = qt * TQ + g, q1 = q0 + 8;
            float2 p0 = *(const float2*)&pos[(size_t)q0 * Ss + gk];
            float2 p1 = *(const float2*)&pos[(size_t)q1 * Ss + gk];
            int2  mm0 = *(const int2*)&mask[(size_t)q0 * Ss + gk];
            int2  mm1 = *(const int2*)&mask[(size_t)q1 * Ss + gk];
            float2 s0, s1;
            s0.x = mm0.x ? fmaf(acc.x, scale, p0.x) : NEG_BIG;
            s0.y = mm0.y ? fmaf(acc.y, scale, p0.y) : NEG_BIG;
            s1.x = mm1.x ? fmaf(acc.z, scale, p1.x) : NEG_BIG;
            s1.y = mm1.y ? fmaf(acc.w, scale, p1.y) : NEG_BIG;
            *(float2*)&sS[g * SPAD + gk] = s0;
            *(float2*)&sS[(g + 8) * SPAD + gk] = s1;
        }
        __syncthreads();
    }

    // ---- softmax per row (8 warps x 2 rows), write attn to gmem ----
    {
        int l = lane;
        #pragma unroll
        for (int r2 = 0; r2 < 2; r2++) {
            int r = w * 2 + r2;
            float4* row = (float4*)&sS[r * SPAD];
            float m = NEG_BIG;
            for (int c = l; c < Ss / 4; c += 32) {
                float4 vv = row[c];
                m = fmaxf(m, fmaxf(fmaxf(vv.x, vv.y), fmaxf(vv.z, vv.w)));
            }
            #pragma unroll
            for (int o = 16; o; o >>= 1) m = fmaxf(m, __shfl_xor_sync(0xFFFFFFFFu, m, o));
            float sum = 0.f;
            for (int c = l; c < Ss / 4; c += 32) {
                float4 vv = row[c];
                vv.x = __expf(vv.x - m); vv.y = __expf(vv.y - m);
                vv.z = __expf(vv.z - m); vv.w = __expf(vv.w - m);
                row[c] = vv;
                sum += vv.x + vv.y + vv.z + vv.w;
            }
            #pragma unroll
            for (int o = 16; o; o >>= 1) sum += __shfl_xor_sync(0xFFFFFFFFu, sum, o);
            float inv = 1.f / sum;
            float4* arow = (float4*)&attn_out[(size_t)r * Ss];
            for (int c = l; c < Ss / 4; c += 32) {
                float4 vv = row[c];
                vv.x *= inv; vv.y *= inv; vv.z *= inv; vv.w *= inv;
                row[c] = vv;
                arow[c] = vv;
            }
        }
    }

    // ---- PV: out[16][64] = P[16][2048] @ V[2048][64] via mma ----
    {
        int n0 = w * 8;                               // this warp's 8 output dims
        float4 oacc = make_float4(0.f, 0.f, 0.f, 0.f);
        for (int kt = 0; kt < Ss / TK; kt++) {
            int kbase = kt * TK;
            __syncthreads();   // first iter: softmax done; later: prev V consumed
            #pragma unroll
            for (int i = 0; i < 8; i++) {
                int idx = tid + i * 256;
                int d4 = idx & 15, key = idx >> 4;
                *(float4*)&sU[key * VPAD + d4 * 4] =
                    *(const float4*)&V[(size_t)(kbase + key) * DK + d4 * 4];
            }
            __syncthreads();
            #pragma unroll
            for (int ks = 0; ks < 16; ks++) {
                int k0 = ks * 8;
                uint32_t a[4];
                a[0] = f2tf32(sS[g * SPAD + kbase + k0 + t]);
                a[1] = f2tf32(sS[(g + 8) * SPAD + kbase + k0 + t]);
                a[2] = f2tf32(sS[g * SPAD + kbase + k0 + t + 4]);
                a[3] = f2tf32(sS[(g + 8) * SPAD + kbase + k0 + t + 4]);
                uint32_t b0 = f2tf32(sU[(k0 + t) * VPAD + n0 + g]);
                uint32_t b1 = f2tf32(sU[(k0 + t + 4) * VPAD + n0 + g]);
                mma_tf32(oacc, a, b0, b1);
            }
        }
        int q0 = qt * TQ + g;
        int col = h * DK + n0 + 2 * t;
        float2 o0 = make_float2(oacc.x, oacc.y);
        float2 o1 = make_float2(oacc.z, oacc.w);
        *(float2*)&g_x[((size_t)(b * Ss + q0)) * Dd + col] = o0;
        *(float2*)&g_x[((size_t)(b * Ss + q0 + 8)) * Dd + col] = o1;
    }
}

// ---------------- Kernel 4: output projection ----------------
__global__ void __launch_bounds__(256) out_proj_kernel(
    const float* __restrict__ W, const float* __restrict__ bias,
    const float* __restrict__ ls, float* __restrict__ Cout) {
    const int BM = 64, BN = 64, BK = 16;
    __shared__ float sA[BK][BM + 4];
    __shared__ float sB[BK][BN + 4];

    int tid = threadIdx.x;
    int tx = tid & 15, ty = tid >> 4;
    int m0 = blockIdx.x * BM, n0 = blockIdx.y * BN;

    float acc[4][4] = {};
    for (int k0 = 0; k0 < Dd; k0 += BK) {
        #pragma unroll
        for (int i = 0; i < 4; i++) {
            int idx = tid + i * 256;
            int kk = idx & 15, m = idx >> 4;
            sA[kk][m] = g_x[(size_t)(m0 + m) * Dd + k0 + kk];
        }
        #pragma unroll
        for (int i = 0; i < 4; i++) {
            int idx = tid + i * 256;
            int n = idx & 63, kk = idx >> 6;
            sB[kk][n] = W[(size_t)(k0 + kk) * Dd + n0 + n];
        }
        __syncthreads();
        #pragma unroll
        for (int kk = 0; kk < BK; kk++) {
            float4 av = *(float4*)&sA[kk][ty * 4];
            float4 bvv = *(float4*)&sB[kk][tx * 4];
            float a[4] = {av.x, av.y, av.z, av.w};
            float bb[4] = {bvv.x, bvv.y, bvv.z, bvv.w};
            #pragma unroll
            for (int i = 0; i < 4; i++)
                #pragma unroll
                for (int j = 0; j < 4; j++)
                    acc[i][j] = fmaf(a[i], bb[j], acc[i][j]);
        }
        __syncthreads();
    }

    int n = n0 + tx * 4;
    float b0 = bias[n], b1 = bias[n+1], b2 = bias[n+2], b3 = bias[n+3];
    float l0 = ls[n], l1 = ls[n+1], l2 = ls[n+2], l3 = ls[n+3];
    #pragma unroll
    for (int i = 0; i < 4; i++) {
        int m = m0 + ty * 4 + i;
        float4 r;
        r.x = (acc[i][0] + b0) * l0;
        r.y = (acc[i][1] + b1) * l1;
        r.z = (acc[i][2] + b2) * l2;
        r.w = (acc[i][3] + b3) * l3;
        *(float4*)&Cout[(size_t)m * Dd + n] = r;
    }
}

// ---------------- launch ----------------
extern "C" void kernel_launch(void* const* d_in, const int* in_sizes, int n_in,
                              void* d_out, int out_size) {
    const float* q    = (const float*)d_in[0];
    const float* k    = (const float*)d_in[1];
    const float* v    = (const float*)d_in[2];
    const int*   mask = (const int*)  d_in[3];
    const float* pos  = (const float*)d_in[4];
    const float* ln_g = (const float*)d_in[5];
    const float* ln_b = (const float*)d_in[6];
    const float* wq   = (const float*)d_in[7];
    const float* bq   = (const float*)d_in[8];
    const float* wk   = (const float*)d_in[9];
    const float* bk   = (const float*)d_in[10];
    const float* wv   = (const float*)d_in[11];
    const float* bv   = (const float*)d_in[12];
    const float* wo   = (const float*)d_in[13];
    const float* bo   = (const float*)d_in[14];
    const float* ls   = (const float*)d_in[15];
    float* out = (float*)d_out;

    size_t smem_bytes = (size_t)SMEM_FLOATS * sizeof(float);   // 170,496 B
    cudaFuncSetAttribute(attn_kernel, cudaFuncAttributeMaxDynamicSharedMemorySize,
                         (int)smem_bytes);

    ln_kernel<<<dim3(BS, 3), 256>>>(q, k, v, ln_g, ln_b);
    qkv_proj_kernel<<<dim3(BS / 64, Dd / 64, 3), 256>>>(wq, wk, wv, bq, bk, bv);
    attn_kernel<<<dim3(Ss / TQ, Hh, Bb), 256, smem_bytes>>>(pos, mask, out);
    out_proj_kernel<<<dim3(BS / 64, Dd / 64), 256>>>(wo, bo, ls, out);
}

// round 3
// speedup vs baseline: 2.3799x; 1.0812x over previous
#include <cuda_runtime.h>
#include <math.h>
#include <stdint.h>

#define Bb 4
#define Ss 2048
#define Dd 512
#define Hh 8
#define DK 64
#define BS (Bb*Ss)          // 8192 rows
#define LN_EPS 1e-5f
#define NEG_BIG (-1e30f)

// ---------------- scratch (static device globals; no allocation) ----------------
__device__ float g_xn[3][(size_t)BS*Dd];                 // normalized q,k,v (tf32-rounded)
__device__ float g_qkvh[3][(size_t)Bb*Hh*Ss*DK];         // head-major Q,K,V (tf32-rounded)
__device__ float g_x[(size_t)BS*Dd];                     // attention output (tf32-rounded)
__device__ float g_wt[4][(size_t)Dd*Dd];                 // W^T, tf32-rounded: [n][k]

// ---------------- helpers ----------------
__device__ __forceinline__ uint32_t f2tf32(float x) {
    uint32_t r;
    asm volatile("cvt.rna.tf32.f32 %0, %1;" : "=r"(r) : "f"(x));
    return r;
}
__device__ __forceinline__ float rnd_tf32(float x) { return __uint_as_float(f2tf32(x)); }

__device__ __forceinline__ void mma_tf32(float4& d, const uint32_t a[4],
                                         uint32_t b0, uint32_t b1) {
    asm volatile(
        "mma.sync.aligned.m16n8k8.row.col.f32.tf32.tf32.f32 "
        "{%0,%1,%2,%3}, {%4,%5,%6,%7}, {%8,%9}, {%0,%1,%2,%3};\n"
        : "+f"(d.x), "+f"(d.y), "+f"(d.z), "+f"(d.w)
        : "r"(a[0]), "r"(a[1]), "r"(a[2]), "r"(a[3]), "r"(b0), "r"(b1));
}

__device__ __forceinline__ void cpa16(float* s, const float* g) {
    uint32_t sa = (uint32_t)__cvta_generic_to_shared(s);
    asm volatile("cp.async.ca.shared.global [%0], [%1], 16;\n" :: "r"(sa), "l"(g));
}
#define CP_COMMIT() asm volatile("cp.async.commit_group;\n")
template<int N> __device__ __forceinline__ void cp_wait() {
    asm volatile("cp.async.wait_group %0;\n" :: "n"(N));
}

// ---------------- Kernel 1: LayerNorm (tf32-rounded output) ----------------
__global__ void ln_kernel(const float* __restrict__ q, const float* __restrict__ k,
                          const float* __restrict__ v, const float* __restrict__ g,
                          const float* __restrict__ b) {
    int row = blockIdx.x;
    int which = blockIdx.y;
    const float* xs = which == 0 ? q : (which == 1 ? k : v);
    const float* x = xs + (size_t)row * Dd;
    float* y = g_xn[which] + (size_t)row * Dd;
    int t = threadIdx.x;

    float v0 = x[t], v1 = x[t + 256];
    float s = v0 + v1, s2 = v0 * v0 + v1 * v1;

    __shared__ float rs[8], rs2[8];
    #pragma unroll
    for (int o = 16; o; o >>= 1) {
        s  += __shfl_xor_sync(0xFFFFFFFFu, s,  o);
        s2 += __shfl_xor_sync(0xFFFFFFFFu, s2, o);
    }
    if ((t & 31) == 0) { rs[t >> 5] = s; rs2[t >> 5] = s2; }
    __syncthreads();
    __shared__ float smu, sinv;
    if (t == 0) {
        float S = 0.f, S2 = 0.f;
        #pragma unroll
        for (int i = 0; i < 8; i++) { S += rs[i]; S2 += rs2[i]; }
        float mu = S * (1.f / 512.f);
        float var = S2 * (1.f / 512.f) - mu * mu;
        smu = mu; sinv = rsqrtf(var + LN_EPS);
    }
    __syncthreads();
    float mu = smu, inv = sinv;
    y[t]       = rnd_tf32((v0 - mu) * inv * g[t]       + b[t]);
    y[t + 256] = rnd_tf32((v1 - mu) * inv * g[t + 256] + b[t + 256]);
}

// ---------------- Kernel 1b: weight transpose + tf32 round ----------------
__global__ void wt_kernel(const float* __restrict__ wq, const float* __restrict__ wk,
                          const float* __restrict__ wv, const float* __restrict__ wo) {
    __shared__ float tile[32][33];
    int z = blockIdx.z;
    const float* W = z == 0 ? wq : (z == 1 ? wk : (z == 2 ? wv : wo));
    int k0 = blockIdx.x * 32, n0 = blockIdx.y * 32;
    int c = threadIdx.x & 31, r0 = threadIdx.x >> 5;
    #pragma unroll
    for (int i = 0; i < 4; i++) {
        int r = r0 + i * 8;
        tile[r][c] = W[(size_t)(k0 + r) * Dd + n0 + c];
    }
    __syncthreads();
    #pragma unroll
    for (int i = 0; i < 4; i++) {
        int r = r0 + i * 8;
        g_wt[z][(size_t)(n0 + r) * Dd + k0 + c] = rnd_tf32(tile[c][r]);
    }
}

// ---------------- tf32 GEMM tile core (BM=64, BN=64, BK=32, 256 thr) ----------------
// A: [M][512] row-major tf32-rounded. Bt: [n][k] tf32-rounded.
__device__ __forceinline__ void gemm_tile_tf32(
    const float* __restrict__ A, const float* __restrict__ Bt,
    int m0, int n0, float4 acc[2][2], float* sA /*[32][72]*/, float* sB /*[64][36]*/) {
    int tid = threadIdx.x;
    int lane = tid & 31, w = tid >> 5;
    int g = lane >> 2, t = lane & 3;
    int wm = w >> 2, wn = w & 3;
    int mw = wm * 32, nw = wn * 16;
    #pragma unroll
    for (int i = 0; i < 2; i++)
        #pragma unroll
        for (int j = 0; j < 2; j++) acc[i][j] = make_float4(0.f, 0.f, 0.f, 0.f);

    for (int k0 = 0; k0 < Dd; k0 += 32) {
        #pragma unroll
        for (int i = 0; i < 2; i++) {
            int idx = tid + i * 256;
            int m = idx >> 3, k4 = idx & 7;
            float4 va = *(const float4*)&A[(size_t)(m0 + m) * Dd + k0 + k4 * 4];
            sA[(k4 * 4 + 0) * 72 + m] = va.x; sA[(k4 * 4 + 1) * 72 + m] = va.y;
            sA[(k4 * 4 + 2) * 72 + m] = va.z; sA[(k4 * 4 + 3) * 72 + m] = va.w;
        }
        #pragma unroll
        for (int i = 0; i < 2; i++) {
            int idx = tid + i * 256;
            int n = idx >> 3, k4 = idx & 7;
            float4 vb = *(const float4*)&Bt[(size_t)(n0 + n) * Dd + k0 + k4 * 4];
            sB[n * 36 + k4 * 4 + 0] = vb.x; sB[n * 36 + k4 * 4 + 1] = vb.y;
            sB[n * 36 + k4 * 4 + 2] = vb.z; sB[n * 36 + k4 * 4 + 3] = vb.w;
        }
        __syncthreads();
        #pragma unroll
        for (int ks = 0; ks < 4; ks++) {
            int kk = ks * 8;
            uint32_t a[2][4];
            #pragma unroll
            for (int mi = 0; mi < 2; mi++) {
                const float* ap  = &sA[(kk + t) * 72 + mw + mi * 16];
                const float* ap2 = &sA[(kk + t + 4) * 72 + mw + mi * 16];
                a[mi][0] = __float_as_uint(ap[g]);
                a[mi][1] = __float_as_uint(ap[g + 8]);
                a[mi][2] = __float_as_uint(ap2[g]);
                a[mi][3] = __float_as_uint(ap2[g + 8]);
            }
            #pragma unroll
            for (int nj = 0; nj < 2; nj++) {
                const float* bp = &sB[(nw + nj * 8 + g) * 36 + kk];
                uint32_t b0 = __float_as_uint(bp[t]);
                uint32_t b1 = __float_as_uint(bp[t + 4]);
                mma_tf32(acc[0][nj], a[0], b0, b1);
                mma_tf32(acc[1][nj], a[1], b0, b1);
            }
        }
        __syncthreads();
    }
}

// ---------------- Kernel 2: QKV projection (tf32 mma, head-major rounded epilogue) ----------------
__global__ void __launch_bounds__(256) proj_qkv_kernel(
    const float* __restrict__ bq, const float* __restrict__ bk, const float* __restrict__ bv) {
    __shared__ float sA[32 * 72];
    __shared__ float sB[64 * 36];
    int z = blockIdx.z;
    const float* bias = z == 0 ? bq : (z == 1 ? bk : bv);
    float* out = g_qkvh[z];
    int m0 = blockIdx.x * 64, n0 = blockIdx.y * 64;

    float4 acc[2][2];
    gemm_tile_tf32(g_xn[z], g_wt[z], m0, n0, acc, sA, sB);

    int lane = threadIdx.x & 31, w = threadIdx.x >> 5;
    int g = lane >> 2, t = lane & 3;
    int wm = w >> 2, wn = w & 3;
    #pragma unroll
    for (int mi = 0; mi < 2; mi++) {
        #pragma unroll
        for (int nj = 0; nj < 2; nj++) {
            int n = n0 + wn * 16 + nj * 8 + 2 * t;
            int hh = n >> 6, dd = n & 63;
            float b0 = bias[n], b1 = bias[n + 1];
            #pragma unroll
            for (int r = 0; r < 2; r++) {
                int m = m0 + wm * 32 + mi * 16 + g + r * 8;
                int bidx = m >> 11, srow = m & 2047;
                float2 val;
                if (r == 0) { val.x = acc[mi][nj].x + b0; val.y = acc[mi][nj].y + b1; }
                else        { val.x = acc[mi][nj].z + b0; val.y = acc[mi][nj].w + b1; }
                val.x = rnd_tf32(val.x); val.y = rnd_tf32(val.y);
                *(float2*)&out[(((size_t)(bidx * Hh + hh) * Ss + srow) * DK) + dd] = val;
            }
        }
    }
}

// ---------------- Kernel 4: output projection (tf32 mma + layer_scale) ----------------
__global__ void __launch_bounds__(256) proj_out_kernel(
    const float* __restrict__ bo, const float* __restrict__ ls, float* __restrict__ Cout) {
    __shared__ float sA[32 * 72];
    __shared__ float sB[64 * 36];
    int m0 = blockIdx.x * 64, n0 = blockIdx.y * 64;

    float4 acc[2][2];
    gemm_tile_tf32(g_x, g_wt[3], m0, n0, acc, sA, sB);

    int lane = threadIdx.x & 31, w = threadIdx.x >> 5;
    int g = lane >> 2, t = lane & 3;
    int wm = w >> 2, wn = w & 3;
    #pragma unroll
    for (int mi = 0; mi < 2; mi++) {
        #pragma unroll
        for (int nj = 0; nj < 2; nj++) {
            int n = n0 + wn * 16 + nj * 8 + 2 * t;
            float b0 = bo[n], b1 = bo[n + 1];
            float l0 = ls[n], l1 = ls[n + 1];
            #pragma unroll
            for (int r = 0; r < 2; r++) {
                int m = m0 + wm * 32 + mi * 16 + g + r * 8;
                float2 val;
                if (r == 0) { val.x = (acc[mi][nj].x + b0) * l0; val.y = (acc[mi][nj].y + b1) * l1; }
                else        { val.x = (acc[mi][nj].z + b0) * l0; val.y = (acc[mi][nj].w + b1) * l1; }
                *(float2*)&Cout[(size_t)m * Dd + n] = val;
            }
        }
    }
}

// ---------------- Kernel 3: attention (512 thr, cp.async double-buffer, no hot-loop cvt) ----------------
#define TQ 16
#define TK 128
#define VPAD 68
#define SPAD 2056
#define SMEM_FLOATS (TQ*SPAD + 2*TK*VPAD + TQ*DK)   // 51328 floats = 205,312 B

__global__ void __launch_bounds__(512, 1) attn_kernel(
    const float* __restrict__ pos, const int* __restrict__ mask, float* __restrict__ d_out) {
    extern __shared__ float smem[];
    float* sS  = smem;                        // [16][SPAD]
    float* sU0 = smem + TQ * SPAD;            // [128][VPAD] buffer 0
    float* sU1 = sU0 + TK * VPAD;             // [128][VPAD] buffer 1
    float* sQ  = sU1 + TK * VPAD;             // [16][64] Q stage / reduction scratch

    int qt = blockIdx.x, h = blockIdx.y, b = blockIdx.z;
    const float* Q = g_qkvh[0] + (size_t)(b * Hh + h) * Ss * DK;
    const float* K = g_qkvh[1] + (size_t)(b * Hh + h) * Ss * DK;
    const float* V = g_qkvh[2] + (size_t)(b * Hh + h) * Ss * DK;
    float* attn_out = d_out + (size_t)BS * Dd
                    + ((size_t)((b * Hh + h) * Ss) + (size_t)qt * TQ) * Ss;

    int tid = threadIdx.x;
    int lane = tid & 31, w = tid >> 5;        // 16 warps
    int g = lane >> 2, t = lane & 3;
    float* bufs[2] = { sU0, sU1 };

    // stage Q tile (1024 floats = 256 float4)
    if (tid < 256) {
        int r = tid >> 4, c4 = tid & 15;
        *(float4*)&sQ[r * DK + c4 * 4] =
            *(const float4*)&Q[(size_t)(qt * TQ + r) * DK + c4 * 4];
    }
    // prefetch K tile 0
    {
        #pragma unroll
        for (int i = 0; i < 4; i++) {
            int idx = tid + i * 512;
            int d4 = idx & 15, key = idx >> 4;
            cpa16(&sU0[key * VPAD + d4 * 4], &K[(size_t)key * DK + d4 * 4]);
        }
        CP_COMMIT();
    }
    __syncthreads();

    // Q fragments in registers (values already tf32-rounded at store)
    uint32_t qa[8][4];
    #pragma unroll
    for (int ks = 0; ks < 8; ks++) {
        int k0 = ks * 8;
        qa[ks][0] = __float_as_uint(sQ[g * DK + k0 + t]);
        qa[ks][1] = __float_as_uint(sQ[(g + 8) * DK + k0 + t]);
        qa[ks][2] = __float_as_uint(sQ[g * DK + k0 + t + 4]);
        qa[ks][3] = __float_as_uint(sQ[(g + 8) * DK + k0 + t + 4]);
    }
    __syncthreads();   // sQ free for later reuse only after all frag reads

    const float scale = 0.125f;

    // ---- QK^T: 16 warps x 8 keys per 128-key tile, double-buffered ----
    for (int kt = 0; kt < Ss / TK; kt++) {
        if (kt < 15) {
            const float* src = &K[(size_t)(kt + 1) * TK * DK];
            float* dst = bufs[(kt + 1) & 1];
            #pragma unroll
            for (int i = 0; i < 4; i++) {
                int idx = tid + i * 512;
                int d4 = idx & 15, key = idx >> 4;
                cpa16(&dst[key * VPAD + d4 * 4], &src[(size_t)key * DK + d4 * 4]);
            }
            CP_COMMIT();
            cp_wait<1>();
        } else {
            cp_wait<0>();
        }
        __syncthreads();

        const float* U = bufs[kt & 1];
        int kbase = kt * TK;
        int n0 = w * 8;
        float4 acc = make_float4(0.f, 0.f, 0.f, 0.f);
        #pragma unroll
        for (int ks = 0; ks < 8; ks++) {
            const float* kp = &U[(n0 + g) * VPAD + ks * 8 + t];
            mma_tf32(acc, qa[ks], __float_as_uint(kp[0]), __float_as_uint(kp[4]));
        }
        int gk = kbase + n0 + 2 * t;
        int q0 = qt * TQ + g, q1 = q0 + 8;
        float2 p0 = *(const float2*)&pos[(size_t)q0 * Ss + gk];
        float2 p1 = *(const float2*)&pos[(size_t)q1 * Ss + gk];
        int2  mm0 = *(const int2*)&mask[(size_t)q0 * Ss + gk];
        int2  mm1 = *(const int2*)&mask[(size_t)q1 * Ss + gk];
        float2 s0, s1;
        s0.x = mm0.x ? fmaf(acc.x, scale, p0.x) : NEG_BIG;
        s0.y = mm0.y ? fmaf(acc.y, scale, p0.y) : NEG_BIG;
        s1.x = mm1.x ? fmaf(acc.z, scale, p1.x) : NEG_BIG;
        s1.y = mm1.y ? fmaf(acc.w, scale, p1.y) : NEG_BIG;
        *(float2*)&sS[g * SPAD + gk] = s0;
        *(float2*)&sS[(g + 8) * SPAD + gk] = s1;
        __syncthreads();
    }

    // prefetch V tile 0 (overlaps softmax)
    {
        #pragma unroll
        for (int i = 0; i < 4; i++) {
            int idx = tid + i * 512;
            int d4 = idx & 15, key = idx >> 4;
            cpa16(&sU0[key * VPAD + d4 * 4], &V[(size_t)key * DK + d4 * 4]);
        }
        CP_COMMIT();
    }

    // ---- softmax: one warp per row; gmem gets exact, sS gets tf32-rounded P ----
    {
        float4* row = (float4*)&sS[w * SPAD];
        float m = NEG_BIG;
        for (int c = lane; c < Ss / 4; c += 32) {
            float4 vv = row[c];
            m = fmaxf(m, fmaxf(fmaxf(vv.x, vv.y), fmaxf(vv.z, vv.w)));
        }
        #pragma unroll
        for (int o = 16; o; o >>= 1) m = fmaxf(m, __shfl_xor_sync(0xFFFFFFFFu, m, o));
        float sum = 0.f;
        for (int c = lane; c < Ss / 4; c += 32) {
            float4 vv = row[c];
            vv.x = __expf(vv.x - m); vv.y = __expf(vv.y - m);
            vv.z = __expf(vv.z - m); vv.w = __expf(vv.w - m);
            row[c] = vv;
            sum += vv.x + vv.y + vv.z + vv.w;
        }
        #pragma unroll
        for (int o = 16; o; o >>= 1) sum += __shfl_xor_sync(0xFFFFFFFFu, sum, o);
        float inv = 1.f / sum;
        float4* arow = (float4*)&attn_out[(size_t)w * Ss];
        for (int c = lane; c < Ss / 4; c += 32) {
            float4 vv = row[c];
            vv.x *= inv; vv.y *= inv; vv.z *= inv; vv.w *= inv;
            arow[c] = vv;                             // exact values to gmem
            vv.x = rnd_tf32(vv.x); vv.y = rnd_tf32(vv.y);
            vv.z = rnd_tf32(vv.z); vv.w = rnd_tf32(vv.w);
            row[c] = vv;                              // rounded P for mma
        }
    }
    __syncthreads();

    // ---- PV: split-k across warp halves, double-buffered V ----
    {
        int kg = (w >> 3) * 64;           // 0 or 64 within each 128-key tile
        int n0 = (w & 7) * 8;             // 8 output dims
        float4 oacc = make_float4(0.f, 0.f, 0.f, 0.f);
        for (int kt = 0; kt < Ss / TK; kt++) {
            if (kt < 15) {
                const float* src = &V[(size_t)(kt + 1) * TK * DK];
                float* dst = bufs[(kt + 1) & 1];
                #pragma unroll
                for (int i = 0; i < 4; i++) {
                    int idx = tid + i * 512;
                    int d4 = idx & 15, key = idx >> 4;
                    cpa16(&dst[key * VPAD + d4 * 4], &src[(size_t)key * DK + d4 * 4]);
                }
                CP_COMMIT();
                cp_wait<1>();
            } else {
                cp_wait<0>();
            }
            __syncthreads();

            const float* U = bufs[kt & 1];
            int kbase = kt * TK;
            #pragma unroll
            for (int ks = 0; ks < 8; ks++) {
                int k0 = kg + ks * 8;
                const float* sr0 = &sS[g * SPAD + kbase + k0 + t];
                const float* sr1 = &sS[(g + 8) * SPAD + kbase + k0 + t];
                uint32_t a[4];
                a[0] = __float_as_uint(sr0[0]);
                a[1] = __float_as_uint(sr1[0]);
                a[2] = __float_as_uint(sr0[4]);
                a[3] = __float_as_uint(sr1[4]);
                uint32_t b0 = __float_as_uint(U[(k0 + t) * VPAD + n0 + g]);
                uint32_t b1 = __float_as_uint(U[(k0 + t + 4) * VPAD + n0 + g]);
                mma_tf32(oacc, a, b0, b1);
            }
            __syncthreads();
        }

        // split-k reduction via sQ scratch
        if (w >= 8) *(float4*)&sQ[(w - 8) * 128 + lane * 4] = oacc;
        __syncthreads();
        if (w < 8) {
            float4 o2 = *(float4*)&sQ[w * 128 + lane * 4];
            oacc.x += o2.x; oacc.y += o2.y; oacc.z += o2.z; oacc.w += o2.w;
            int q0 = qt * TQ + g;
            int col = h * DK + n0 + 2 * t;
            float2 r0, r1;
            r0.x = rnd_tf32(oacc.x); r0.y = rnd_tf32(oacc.y);
            r1.x = rnd_tf32(oacc.z); r1.y = rnd_tf32(oacc.w);
            *(float2*)&g_x[((size_t)(b * Ss + q0)) * Dd + col] = r0;
            *(float2*)&g_x[((size_t)(b * Ss + q0 + 8)) * Dd + col] = r1;
        }
    }
}

// ---------------- launch ----------------
extern "C" void kernel_launch(void* const* d_in, const int* in_sizes, int n_in,
                              void* d_out, int out_size) {
    const float* q    = (const float*)d_in[0];
    const float* k    = (const float*)d_in[1];
    const float* v    = (const float*)d_in[2];
    const int*   mask = (const int*)  d_in[3];
    const float* pos  = (const float*)d_in[4];
    const float* ln_g = (const float*)d_in[5];
    const float* ln_b = (const float*)d_in[6];
    const float* wq   = (const float*)d_in[7];
    const float* bq   = (const float*)d_in[8];
    const float* wk   = (const float*)d_in[9];
    const float* bk   = (const float*)d_in[10];
    const float* wv   = (const float*)d_in[11];
    const float* bv   = (const float*)d_in[12];
    const float* wo   = (const float*)d_in[13];
    const float* bo   = (const float*)d_in[14];
    const float* ls   = (const float*)d_in[15];
    float* out = (float*)d_out;

    size_t smem_bytes = (size_t)SMEM_FLOATS * sizeof(float);   // 205,312 B
    cudaFuncSetAttribute(attn_kernel, cudaFuncAttributeMaxDynamicSharedMemorySize,
                         (int)smem_bytes);

    ln_kernel<<<dim3(BS, 3), 256>>>(q, k, v, ln_g, ln_b);
    wt_kernel<<<dim3(16, 16, 4), 256>>>(wq, wk, wv, wo);
    proj_qkv_kernel<<<dim3(BS / 64, Dd / 64, 3), 256>>>(bq, bk, bv);
    attn_kernel<<<dim3(Ss / TQ, Hh, Bb), 512, smem_bytes>>>(pos, mask, out);
    proj_out_kernel<<<dim3(BS / 64, Dd / 64), 256>>>(bo, ls, out);
}

// round 4
// speedup vs baseline: 2.4450x; 1.0274x over previous
#include <cuda_runtime.h>
#include <math.h>
#include <stdint.h>

#define Bb 4
#define Ss 2048
#define Dd 512
#define Hh 8
#define DK 64
#define BS (Bb*Ss)          // 8192 rows
#define LN_EPS 1e-5f
#define NEG_BIG (-1e30f)

// ---------------- scratch (static device globals; no allocation) ----------------
__device__ float g_xn[3][(size_t)BS*Dd];                 // normalized q,k,v (tf32-rounded)
__device__ float g_qkvh[3][(size_t)Bb*Hh*Ss*DK];         // head-major Q,K,V (tf32-rounded)
__device__ float g_x[(size_t)BS*Dd];                     // attention output (tf32-rounded)
__device__ float g_wt[4][(size_t)Dd*Dd];                 // W^T, tf32-rounded: [n][k]
__device__ float g_bias[(size_t)Ss*Ss];                  // mask? pos : -1e30  (16.8 MB)

// ---------------- helpers ----------------
__device__ __forceinline__ uint32_t f2tf32(float x) {
    uint32_t r;
    asm volatile("cvt.rna.tf32.f32 %0, %1;" : "=r"(r) : "f"(x));
    return r;
}
__device__ __forceinline__ float rnd_tf32(float x) { return __uint_as_float(f2tf32(x)); }

__device__ __forceinline__ void mma_tf32(float4& d, const uint32_t a[4],
                                         uint32_t b0, uint32_t b1) {
    asm volatile(
        "mma.sync.aligned.m16n8k8.row.col.f32.tf32.tf32.f32 "
        "{%0,%1,%2,%3}, {%4,%5,%6,%7}, {%8,%9}, {%0,%1,%2,%3};\n"
        : "+f"(d.x), "+f"(d.y), "+f"(d.z), "+f"(d.w)
        : "r"(a[0]), "r"(a[1]), "r"(a[2]), "r"(a[3]), "r"(b0), "r"(b1));
}

__device__ __forceinline__ void cpa16(float* s, const float* g) {
    uint32_t sa = (uint32_t)__cvta_generic_to_shared(s);
    asm volatile("cp.async.ca.shared.global [%0], [%1], 16;\n" :: "r"(sa), "l"(g));
}
#define CP_COMMIT() asm volatile("cp.async.commit_group;\n")
template<int N> __device__ __forceinline__ void cp_wait() {
    asm volatile("cp.async.wait_group %0;\n" :: "n"(N));
}

// FMA-pipe exp: exp(x) for x <= 0 (post max-subtraction). ~1e-7 rel err.
// Avoids MUFU entirely (MUFU rt=8/SMSP is the round-3 bottleneck).
__device__ __forceinline__ float fast_exp(float x) {
    x = fmaxf(x, -87.0f);                       // masked -1e30 -> exp ~ 1.6e-38 ~ 0
    float t = x * 1.4426950408889634f;          // log2(e)
    float z = t + 12582912.0f;                  // 1.5*2^23: round-to-nearest int
    float f = t - (z - 12582912.0f);            // frac in [-0.5, 0.5]
    int   e = __float_as_int(z) - 0x4B400000;   // round(t)
    float p = 1.33335581e-3f;
    p = fmaf(p, f, 9.61812910e-3f);
    p = fmaf(p, f, 5.55041087e-2f);
    p = fmaf(p, f, 2.40226507e-1f);
    p = fmaf(p, f, 6.93147180e-1f);
    p = fmaf(p, f, 1.0f);
    return __int_as_float((e + 127) << 23) * p;
}

// ---------------- Kernel 0: fuse mask+pos into additive bias ----------------
__global__ void bias_kernel(const float* __restrict__ pos, const int* __restrict__ mask) {
    size_t i = (size_t)blockIdx.x * 1024 + threadIdx.x;
    float4 p = *(const float4*)&pos[i * 4];
    int4   m = *(const int4*)&mask[i * 4];
    float4 o;
    o.x = m.x ? p.x : NEG_BIG;
    o.y = m.y ? p.y : NEG_BIG;
    o.z = m.z ? p.z : NEG_BIG;
    o.w = m.w ? p.w : NEG_BIG;
    *(float4*)&g_bias[i * 4] = o;
}

// ---------------- Kernel 1: LayerNorm (tf32-rounded output) ----------------
__global__ void ln_kernel(const float* __restrict__ q, const float* __restrict__ k,
                          const float* __restrict__ v, const float* __restrict__ g,
                          const float* __restrict__ b) {
    int row = blockIdx.x;
    int which = blockIdx.y;
    const float* xs = which == 0 ? q : (which == 1 ? k : v);
    const float* x = xs + (size_t)row * Dd;
    float* y = g_xn[which] + (size_t)row * Dd;
    int t = threadIdx.x;

    float v0 = x[t], v1 = x[t + 256];
    float s = v0 + v1, s2 = v0 * v0 + v1 * v1;

    __shared__ float rs[8], rs2[8];
    #pragma unroll
    for (int o = 16; o; o >>= 1) {
        s  += __shfl_xor_sync(0xFFFFFFFFu, s,  o);
        s2 += __shfl_xor_sync(0xFFFFFFFFu, s2, o);
    }
    if ((t & 31) == 0) { rs[t >> 5] = s; rs2[t >> 5] = s2; }
    __syncthreads();
    __shared__ float smu, sinv;
    if (t == 0) {
        float S = 0.f, S2 = 0.f;
        #pragma unroll
        for (int i = 0; i < 8; i++) { S += rs[i]; S2 += rs2[i]; }
        float mu = S * (1.f / 512.f);
        float var = S2 * (1.f / 512.f) - mu * mu;
        smu = mu; sinv = rsqrtf(var + LN_EPS);
    }
    __syncthreads();
    float mu = smu, inv = sinv;
    y[t]       = rnd_tf32((v0 - mu) * inv * g[t]       + b[t]);
    y[t + 256] = rnd_tf32((v1 - mu) * inv * g[t + 256] + b[t + 256]);
}

// ---------------- Kernel 1b: weight transpose + tf32 round ----------------
__global__ void wt_kernel(const float* __restrict__ wq, const float* __restrict__ wk,
                          const float* __restrict__ wv, const float* __restrict__ wo) {
    __shared__ float tile[32][33];
    int z = blockIdx.z;
    const float* W = z == 0 ? wq : (z == 1 ? wk : (z == 2 ? wv : wo));
    int k0 = blockIdx.x * 32, n0 = blockIdx.y * 32;
    int c = threadIdx.x & 31, r0 = threadIdx.x >> 5;
    #pragma unroll
    for (int i = 0; i < 4; i++) {
        int r = r0 + i * 8;
        tile[r][c] = W[(size_t)(k0 + r) * Dd + n0 + c];
    }
    __syncthreads();
    #pragma unroll
    for (int i = 0; i < 4; i++) {
        int r = r0 + i * 8;
        g_wt[z][(size_t)(n0 + r) * Dd + k0 + c] = rnd_tf32(tile[c][r]);
    }
}

// ---------------- tf32 GEMM tile core (BM=64, BN=64, BK=32, 256 thr) ----------------
__device__ __forceinline__ void gemm_tile_tf32(
    const float* __restrict__ A, const float* __restrict__ Bt,
    int m0, int n0, float4 acc[2][2], float* sA /*[32][72]*/, float* sB /*[64][36]*/) {
    int tid = threadIdx.x;
    int lane = tid & 31, w = tid >> 5;
    int g = lane >> 2, t = lane & 3;
    int wm = w >> 2, wn = w & 3;
    int mw = wm * 32, nw = wn * 16;
    #pragma unroll
    for (int i = 0; i < 2; i++)
        #pragma unroll
        for (int j = 0; j < 2; j++) acc[i][j] = make_float4(0.f, 0.f, 0.f, 0.f);

    for (int k0 = 0; k0 < Dd; k0 += 32) {
        #pragma unroll
        for (int i = 0; i < 2; i++) {
            int idx = tid + i * 256;
            int m = idx >> 3, k4 = idx & 7;
            float4 va = *(const float4*)&A[(size_t)(m0 + m) * Dd + k0 + k4 * 4];
            sA[(k4 * 4 + 0) * 72 + m] = va.x; sA[(k4 * 4 + 1) * 72 + m] = va.y;
            sA[(k4 * 4 + 2) * 72 + m] = va.z; sA[(k4 * 4 + 3) * 72 + m] = va.w;
        }
        #pragma unroll
        for (int i = 0; i < 2; i++) {
            int idx = tid + i * 256;
            int n = idx >> 3, k4 = idx & 7;
            float4 vb = *(const float4*)&Bt[(size_t)(n0 + n) * Dd + k0 + k4 * 4];
            sB[n * 36 + k4 * 4 + 0] = vb.x; sB[n * 36 + k4 * 4 + 1] = vb.y;
            sB[n * 36 + k4 * 4 + 2] = vb.z; sB[n * 36 + k4 * 4 + 3] = vb.w;
        }
        __syncthreads();
        #pragma unroll
        for (int ks = 0; ks < 4; ks++) {
            int kk = ks * 8;
            uint32_t a[2][4];
            #pragma unroll
            for (int mi = 0; mi < 2; mi++) {
                const float* ap  = &sA[(kk + t) * 72 + mw + mi * 16];
                const float* ap2 = &sA[(kk + t + 4) * 72 + mw + mi * 16];
                a[mi][0] = __float_as_uint(ap[g]);
                a[mi][1] = __float_as_uint(ap[g + 8]);
                a[mi][2] = __float_as_uint(ap2[g]);
                a[mi][3] = __float_as_uint(ap2[g + 8]);
            }
            #pragma unroll
            for (int nj = 0; nj < 2; nj++) {
                const float* bp = &sB[(nw + nj * 8 + g) * 36 + kk];
                uint32_t b0 = __float_as_uint(bp[t]);
                uint32_t b1 = __float_as_uint(bp[t + 4]);
                mma_tf32(acc[0][nj], a[0], b0, b1);
                mma_tf32(acc[1][nj], a[1], b0, b1);
            }
        }
        __syncthreads();
    }
}

// ---------------- Kernel 2: QKV projection (tf32 mma, head-major rounded epilogue) ----------------
__global__ void __launch_bounds__(256) proj_qkv_kernel(
    const float* __restrict__ bq, const float* __restrict__ bk, const float* __restrict__ bv) {
    __shared__ float sA[32 * 72];
    __shared__ float sB[64 * 36];
    int z = blockIdx.z;
    const float* bias = z == 0 ? bq : (z == 1 ? bk : bv);
    float* out = g_qkvh[z];
    int m0 = blockIdx.x * 64, n0 = blockIdx.y * 64;

    float4 acc[2][2];
    gemm_tile_tf32(g_xn[z], g_wt[z], m0, n0, acc, sA, sB);

    int lane = threadIdx.x & 31, w = threadIdx.x >> 5;
    int g = lane >> 2, t = lane & 3;
    int wm = w >> 2, wn = w & 3;
    #pragma unroll
    for (int mi = 0; mi < 2; mi++) {
        #pragma unroll
        for (int nj = 0; nj < 2; nj++) {
            int n = n0 + wn * 16 + nj * 8 + 2 * t;
            int hh = n >> 6, dd = n & 63;
            float b0 = bias[n], b1 = bias[n + 1];
            #pragma unroll
            for (int r = 0; r < 2; r++) {
                int m = m0 + wm * 32 + mi * 16 + g + r * 8;
                int bidx = m >> 11, srow = m & 2047;
                float2 val;
                if (r == 0) { val.x = acc[mi][nj].x + b0; val.y = acc[mi][nj].y + b1; }
                else        { val.x = acc[mi][nj].z + b0; val.y = acc[mi][nj].w + b1; }
                val.x = rnd_tf32(val.x); val.y = rnd_tf32(val.y);
                *(float2*)&out[(((size_t)(bidx * Hh + hh) * Ss + srow) * DK) + dd] = val;
            }
        }
    }
}

// ---------------- Kernel 4: output projection (tf32 mma + layer_scale) ----------------
__global__ void __launch_bounds__(256) proj_out_kernel(
    const float* __restrict__ bo, const float* __restrict__ ls, float* __restrict__ Cout) {
    __shared__ float sA[32 * 72];
    __shared__ float sB[64 * 36];
    int m0 = blockIdx.x * 64, n0 = blockIdx.y * 64;

    float4 acc[2][2];
    gemm_tile_tf32(g_x, g_wt[3], m0, n0, acc, sA, sB);

    int lane = threadIdx.x & 31, w = threadIdx.x >> 5;
    int g = lane >> 2, t = lane & 3;
    int wm = w >> 2, wn = w & 3;
    #pragma unroll
    for (int mi = 0; mi < 2; mi++) {
        #pragma unroll
        for (int nj = 0; nj < 2; nj++) {
            int n = n0 + wn * 16 + nj * 8 + 2 * t;
            float b0 = bo[n], b1 = bo[n + 1];
            float l0 = ls[n], l1 = ls[n + 1];
            #pragma unroll
            for (int r = 0; r < 2; r++) {
                int m = m0 + wm * 32 + mi * 16 + g + r * 8;
                float2 val;
                if (r == 0) { val.x = (acc[mi][nj].x + b0) * l0; val.y = (acc[mi][nj].y + b1) * l1; }
                else        { val.x = (acc[mi][nj].z + b0) * l0; val.y = (acc[mi][nj].w + b1) * l1; }
                *(float2*)&Cout[(size_t)m * Dd + n] = val;
            }
        }
    }
}

// ---------------- Kernel 3: attention (512 thr, cp.async double-buffer, FMA-pipe exp) ----------------
#define TQ 16
#define TK 128
#define VPAD 68
#define SPAD 2056
#define SMEM_FLOATS (TQ*SPAD + 2*TK*VPAD + TQ*DK)   // 51328 floats = 205,312 B

__global__ void __launch_bounds__(512, 1) attn_kernel(float* __restrict__ d_out) {
    extern __shared__ float smem[];
    float* sS  = smem;                        // [16][SPAD]
    float* sU0 = smem + TQ * SPAD;            // [128][VPAD] buffer 0
    float* sU1 = sU0 + TK * VPAD;             // [128][VPAD] buffer 1
    float* sQ  = sU1 + TK * VPAD;             // [16][64] Q stage / reduction scratch

    int qt = blockIdx.x, h = blockIdx.y, b = blockIdx.z;
    const float* Q = g_qkvh[0] + (size_t)(b * Hh + h) * Ss * DK;
    const float* K = g_qkvh[1] + (size_t)(b * Hh + h) * Ss * DK;
    const float* V = g_qkvh[2] + (size_t)(b * Hh + h) * Ss * DK;
    float* attn_out = d_out + (size_t)BS * Dd
                    + ((size_t)((b * Hh + h) * Ss) + (size_t)qt * TQ) * Ss;

    int tid = threadIdx.x;
    int lane = tid & 31, w = tid >> 5;        // 16 warps
    int g = lane >> 2, t = lane & 3;
    float* bufs[2] = { sU0, sU1 };

    // stage Q tile
    if (tid < 256) {
        int r = tid >> 4, c4 = tid & 15;
        *(float4*)&sQ[r * DK + c4 * 4] =
            *(const float4*)&Q[(size_t)(qt * TQ + r) * DK + c4 * 4];
    }
    // prefetch K tile 0
    {
        #pragma unroll
        for (int i = 0; i < 4; i++) {
            int idx = tid + i * 512;
            int d4 = idx & 15, key = idx >> 4;
            cpa16(&sU0[key * VPAD + d4 * 4], &K[(size_t)key * DK + d4 * 4]);
        }
        CP_COMMIT();
    }
    __syncthreads();

    // Q fragments in registers
    uint32_t qa[8][4];
    #pragma unroll
    for (int ks = 0; ks < 8; ks++) {
        int k0 = ks * 8;
        qa[ks][0] = __float_as_uint(sQ[g * DK + k0 + t]);
        qa[ks][1] = __float_as_uint(sQ[(g + 8) * DK + k0 + t]);
        qa[ks][2] = __float_as_uint(sQ[g * DK + k0 + t + 4]);
        qa[ks][3] = __float_as_uint(sQ[(g + 8) * DK + k0 + t + 4]);
    }
    __syncthreads();

    const float scale = 0.125f;

    // ---- QK^T with fused bias, double-buffered ----
    for (int kt = 0; kt < Ss / TK; kt++) {
        if (kt < 15) {
            const float* src = &K[(size_t)(kt + 1) * TK * DK];
            float* dst = bufs[(kt + 1) & 1];
            #pragma unroll
            for (int i = 0; i < 4; i++) {
                int idx = tid + i * 512;
                int d4 = idx & 15, key = idx >> 4;
                cpa16(&dst[key * VPAD + d4 * 4], &src[(size_t)key * DK + d4 * 4]);
            }
            CP_COMMIT();
            cp_wait<1>();
        } else {
            cp_wait<0>();
        }
        __syncthreads();

        const float* U = bufs[kt & 1];
        int kbase = kt * TK;
        int n0 = w * 8;
        float4 acc = make_float4(0.f, 0.f, 0.f, 0.f);
        #pragma unroll
        for (int ks = 0; ks < 8; ks++) {
            const float* kp = &U[(n0 + g) * VPAD + ks * 8 + t];
            mma_tf32(acc, qa[ks], __float_as_uint(kp[0]), __float_as_uint(kp[4]));
        }
        int gk = kbase + n0 + 2 * t;
        int q0 = qt * TQ + g, q1 = q0 + 8;
        float2 p0 = *(const float2*)&g_bias[(size_t)q0 * Ss + gk];
        float2 p1 = *(const float2*)&g_bias[(size_t)q1 * Ss + gk];
        float2 s0, s1;
        s0.x = fmaf(acc.x, scale, p0.x);
        s0.y = fmaf(acc.y, scale, p0.y);
        s1.x = fmaf(acc.z, scale, p1.x);
        s1.y = fmaf(acc.w, scale, p1.y);
        *(float2*)&sS[g * SPAD + gk] = s0;
        *(float2*)&sS[(g + 8) * SPAD + gk] = s1;
        __syncthreads();
    }

    // prefetch V tile 0 (overlaps softmax)
    {
        #pragma unroll
        for (int i = 0; i < 4; i++) {
            int idx = tid + i * 512;
            int d4 = idx & 15, key = idx >> 4;
            cpa16(&sU0[key * VPAD + d4 * 4], &V[(size_t)key * DK + d4 * 4]);
        }
        CP_COMMIT();
    }

    // ---- softmax (FMA-pipe exp): one warp per row ----
    {
        float4* row = (float4*)&sS[w * SPAD];
        float m = NEG_BIG;
        for (int c = lane; c < Ss / 4; c += 32) {
            float4 vv = row[c];
            m = fmaxf(m, fmaxf(fmaxf(vv.x, vv.y), fmaxf(vv.z, vv.w)));
        }
        #pragma unroll
        for (int o = 16; o; o >>= 1) m = fmaxf(m, __shfl_xor_sync(0xFFFFFFFFu, m, o));
        float sum = 0.f;
        for (int c = lane; c < Ss / 4; c += 32) {
            float4 vv = row[c];
            vv.x = fast_exp(vv.x - m); vv.y = fast_exp(vv.y - m);
            vv.z = fast_exp(vv.z - m); vv.w = fast_exp(vv.w - m);
            row[c] = vv;
            sum += vv.x + vv.y + vv.z + vv.w;
        }
        #pragma unroll
        for (int o = 16; o; o >>= 1) sum += __shfl_xor_sync(0xFFFFFFFFu, sum, o);
        float inv = 1.f / sum;
        float4* arow = (float4*)&attn_out[(size_t)w * Ss];
        for (int c = lane; c < Ss / 4; c += 32) {
            float4 vv = row[c];
            vv.x *= inv; vv.y *= inv; vv.z *= inv; vv.w *= inv;
            arow[c] = vv;                             // exact values to gmem
            vv.x = rnd_tf32(vv.x); vv.y = rnd_tf32(vv.y);
            vv.z = rnd_tf32(vv.z); vv.w = rnd_tf32(vv.w);
            row[c] = vv;                              // rounded P for mma
        }
    }
    __syncthreads();

    // ---- PV: split-k across warp halves, double-buffered V ----
    {
        int kg = (w >> 3) * 64;
        int n0 = (w & 7) * 8;
        float4 oacc = make_float4(0.f, 0.f, 0.f, 0.f);
        for (int kt = 0; kt < Ss / TK; kt++) {
            if (kt < 15) {
                const float* src = &V[(size_t)(kt + 1) * TK * DK];
                float* dst = bufs[(kt + 1) & 1];
                #pragma unroll
                for (int i = 0; i < 4; i++) {
                    int idx = tid + i * 512;
                    int d4 = idx & 15, key = idx >> 4;
                    cpa16(&dst[key * VPAD + d4 * 4], &src[(size_t)key * DK + d4 * 4]);
                }
                CP_COMMIT();
                cp_wait<1>();
            } else {
                cp_wait<0>();
            }
            __syncthreads();

            const float* U = bufs[kt & 1];
            int kbase = kt * TK;
            #pragma unroll
            for (int ks = 0; ks < 8; ks++) {
                int k0 = kg + ks * 8;
                const float* sr0 = &sS[g * SPAD + kbase + k0 + t];
                const float* sr1 = &sS[(g + 8) * SPAD + kbase + k0 + t];
                uint32_t a[4];
                a[0] = __float_as_uint(sr0[0]);
                a[1] = __float_as_uint(sr1[0]);
                a[2] = __float_as_uint(sr0[4]);
                a[3] = __float_as_uint(sr1[4]);
                uint32_t b0 = __float_as_uint(U[(k0 + t) * VPAD + n0 + g]);
                uint32_t b1 = __float_as_uint(U[(k0 + t + 4) * VPAD + n0 + g]);
                mma_tf32(oacc, a, b0, b1);
            }
            __syncthreads();
        }

        if (w >= 8) *(float4*)&sQ[(w - 8) * 128 + lane * 4] = oacc;
        __syncthreads();
        if (w < 8) {
            float4 o2 = *(float4*)&sQ[w * 128 + lane * 4];
            oacc.x += o2.x; oacc.y += o2.y; oacc.z += o2.z; oacc.w += o2.w;
            int q0 = qt * TQ + g;
            int col = h * DK + n0 + 2 * t;
            float2 r0, r1;
            r0.x = rnd_tf32(oacc.x); r0.y = rnd_tf32(oacc.y);
            r1.x = rnd_tf32(oacc.z); r1.y = rnd_tf32(oacc.w);
            *(float2*)&g_x[((size_t)(b * Ss + q0)) * Dd + col] = r0;
            *(float2*)&g_x[((size_t)(b * Ss + q0 + 8)) * Dd + col] = r1;
        }
    }
}

// ---------------- launch ----------------
extern "C" void kernel_launch(void* const* d_in, const int* in_sizes, int n_in,
                              void* d_out, int out_size) {
    const float* q    = (const float*)d_in[0];
    const float* k    = (const float*)d_in[1];
    const float* v    = (const float*)d_in[2];
    const int*   mask = (const int*)  d_in[3];
    const float* pos  = (const float*)d_in[4];
    const float* ln_g = (const float*)d_in[5];
    const float* ln_b = (const float*)d_in[6];
    const float* wq   = (const float*)d_in[7];
    const float* bq   = (const float*)d_in[8];
    const float* wk   = (const float*)d_in[9];
    const float* bk   = (const float*)d_in[10];
    const float* wv   = (const float*)d_in[11];
    const float* bv   = (const float*)d_in[12];
    const float* wo   = (const float*)d_in[13];
    const float* bo   = (const float*)d_in[14];
    const float* ls   = (const float*)d_in[15];
    float* out = (float*)d_out;

    size_t smem_bytes = (size_t)SMEM_FLOATS * sizeof(float);   // 205,312 B
    cudaFuncSetAttribute(attn_kernel, cudaFuncAttributeMaxDynamicSharedMemorySize,
                         (int)smem_bytes);

    bias_kernel<<<(Ss * (size_t)Ss) / 4096, 1024>>>(pos, mask);
    ln_kernel<<<dim3(BS, 3), 256>>>(q, k, v, ln_g, ln_b);
    wt_kernel<<<dim3(16, 16, 4), 256>>>(wq, wk, wv, wo);
    proj_qkv_kernel<<<dim3(BS / 64, Dd / 64, 3), 256>>>(bq, bk, bv);
    attn_kernel<<<dim3(Ss / TQ, Hh, Bb), 512, smem_bytes>>>(out);
    proj_out_kernel<<<dim3(BS / 64, Dd / 64), 256>>>(bo, ls, out);
}

// round 6
// speedup vs baseline: 2.8491x; 1.1653x over previous
#include <cuda_runtime.h>
#include <math.h>
#include <stdint.h>

#define Bb 4
#define Ss 2048
#define Dd 512
#define Hh 8
#define DK 64
#define BS (Bb*Ss)          // 8192 rows
#define LN_EPS 1e-5f
#define NEG_BIG (-1e30f)

// ---------------- scratch (static device globals; no allocation) ----------------
__device__ float g_xn[3][(size_t)BS*Dd];                 // normalized q,k,v (tf32-rounded)
__device__ float g_qkvh[3][(size_t)Bb*Hh*Ss*DK];         // head-major Q,K,V (tf32-rounded)
__device__ float g_x[(size_t)BS*Dd];                     // attention output (tf32-rounded)
__device__ float g_wt[4][(size_t)Dd*Dd];                 // W^T, tf32-rounded: [n][k]
__device__ float g_bias[(size_t)Ss*Ss];                  // mask? pos : -1e30  (16.8 MB)

// ---------------- helpers ----------------
__device__ __forceinline__ uint32_t f2tf32(float x) {
    uint32_t r;
    asm volatile("cvt.rna.tf32.f32 %0, %1;" : "=r"(r) : "f"(x));
    return r;
}
__device__ __forceinline__ float rnd_tf32(float x) { return __uint_as_float(f2tf32(x)); }

__device__ __forceinline__ void mma_tf32(float4& d, const uint32_t a[4],
                                         uint32_t b0, uint32_t b1) {
    asm volatile(
        "mma.sync.aligned.m16n8k8.row.col.f32.tf32.tf32.f32 "
        "{%0,%1,%2,%3}, {%4,%5,%6,%7}, {%8,%9}, {%0,%1,%2,%3};\n"
        : "+f"(d.x), "+f"(d.y), "+f"(d.z), "+f"(d.w)
        : "r"(a[0]), "r"(a[1]), "r"(a[2]), "r"(a[3]), "r"(b0), "r"(b1));
}

// FMA-pipe exp; safe for any x (clamped below), ~1e-7 rel err.
__device__ __forceinline__ float fast_exp(float x) {
    x = fmaxf(x, -87.0f);                       // masked -1e30 -> ~0
    float t = x * 1.4426950408889634f;
    float z = t + 12582912.0f;
    float f = t - (z - 12582912.0f);
    int   e = __float_as_int(z) - 0x4B400000;
    float p = 1.33335581e-3f;
    p = fmaf(p, f, 9.61812910e-3f);
    p = fmaf(p, f, 5.55041087e-2f);
    p = fmaf(p, f, 2.40226507e-1f);
    p = fmaf(p, f, 6.93147180e-1f);
    p = fmaf(p, f, 1.0f);
    return __int_as_float((e + 127) << 23) * p;
}

// ---------------- Kernel 0: fuse mask+pos into additive bias ----------------
__global__ void bias_kernel(const float* __restrict__ pos, const int* __restrict__ mask) {
    size_t i = (size_t)blockIdx.x * 1024 + threadIdx.x;
    float4 p = *(const float4*)&pos[i * 4];
    int4   m = *(const int4*)&mask[i * 4];
    float4 o;
    o.x = m.x ? p.x : NEG_BIG;
    o.y = m.y ? p.y : NEG_BIG;
    o.z = m.z ? p.z : NEG_BIG;
    o.w = m.w ? p.w : NEG_BIG;
    *(float4*)&g_bias[i * 4] = o;
}

// ---------------- Kernel 1: LayerNorm (tf32-rounded output) ----------------
__global__ void ln_kernel(const float* __restrict__ q, const float* __restrict__ k,
                          const float* __restrict__ v, const float* __restrict__ g,
                          const float* __restrict__ b) {
    int row = blockIdx.x;
    int which = blockIdx.y;
    const float* xs = which == 0 ? q : (which == 1 ? k : v);
    const float* x = xs + (size_t)row * Dd;
    float* y = g_xn[which] + (size_t)row * Dd;
    int t = threadIdx.x;

    float v0 = x[t], v1 = x[t + 256];
    float s = v0 + v1, s2 = v0 * v0 + v1 * v1;

    __shared__ float rs[8], rs2[8];
    #pragma unroll
    for (int o = 16; o; o >>= 1) {
        s  += __shfl_xor_sync(0xFFFFFFFFu, s,  o);
        s2 += __shfl_xor_sync(0xFFFFFFFFu, s2, o);
    }
    if ((t & 31) == 0) { rs[t >> 5] = s; rs2[t >> 5] = s2; }
    __syncthreads();
    __shared__ float smu, sinv;
    if (t == 0) {
        float S = 0.f, S2 = 0.f;
        #pragma unroll
        for (int i = 0; i < 8; i++) { S += rs[i]; S2 += rs2[i]; }
        float mu = S * (1.f / 512.f);
        float var = S2 * (1.f / 512.f) - mu * mu;
        smu = mu; sinv = rsqrtf(var + LN_EPS);
    }
    __syncthreads();
    float mu = smu, inv = sinv;
    y[t]       = rnd_tf32((v0 - mu) * inv * g[t]       + b[t]);
    y[t + 256] = rnd_tf32((v1 - mu) * inv * g[t + 256] + b[t + 256]);
}

// ---------------- Kernel 1b: weight transpose + tf32 round ----------------
__global__ void wt_kernel(const float* __restrict__ wq, const float* __restrict__ wk,
                          const float* __restrict__ wv, const float* __restrict__ wo) {
    __shared__ float tile[32][33];
    int z = blockIdx.z;
    const float* W = z == 0 ? wq : (z == 1 ? wk : (z == 2 ? wv : wo));
    int k0 = blockIdx.x * 32, n0 = blockIdx.y * 32;
    int c = threadIdx.x & 31, r0 = threadIdx.x >> 5;
    #pragma unroll
    for (int i = 0; i < 4; i++) {
        int r = r0 + i * 8;
        tile[r][c] = W[(size_t)(k0 + r) * Dd + n0 + c];
    }
    __syncthreads();
    #pragma unroll
    for (int i = 0; i < 4; i++) {
        int r = r0 + i * 8;
        g_wt[z][(size_t)(n0 + r) * Dd + k0 + c] = rnd_tf32(tile[c][r]);
    }
}

// ---------------- tf32 GEMM tile core (BM=64, BN=64, BK=32, 256 thr) ----------------
__device__ __forceinline__ void gemm_tile_tf32(
    const float* __restrict__ A, const float* __restrict__ Bt,
    int m0, int n0, float4 acc[2][2], float* sA /*[32][72]*/, float* sB /*[64][36]*/) {
    int tid = threadIdx.x;
    int lane = tid & 31, w = tid >> 5;
    int g = lane >> 2, t = lane & 3;
    int wm = w >> 2, wn = w & 3;
    int mw = wm * 32, nw = wn * 16;
    #pragma unroll
    for (int i = 0; i < 2; i++)
        #pragma unroll
        for (int j = 0; j < 2; j++) acc[i][j] = make_float4(0.f, 0.f, 0.f, 0.f);

    for (int k0 = 0; k0 < Dd; k0 += 32) {
        #pragma unroll
        for (int i = 0; i < 2; i++) {
            int idx = tid + i * 256;
            int m = idx >> 3, k4 = idx & 7;
            float4 va = *(const float4*)&A[(size_t)(m0 + m) * Dd + k0 + k4 * 4];
            sA[(k4 * 4 + 0) * 72 + m] = va.x; sA[(k4 * 4 + 1) * 72 + m] = va.y;
            sA[(k4 * 4 + 2) * 72 + m] = va.z; sA[(k4 * 4 + 3) * 72 + m] = va.w;
        }
        #pragma unroll
        for (int i = 0; i < 2; i++) {
            int idx = tid + i * 256;
            int n = idx >> 3, k4 = idx & 7;
            float4 vb = *(const float4*)&Bt[(size_t)(n0 + n) * Dd + k0 + k4 * 4];
            sB[n * 36 + k4 * 4 + 0] = vb.x; sB[n * 36 + k4 * 4 + 1] = vb.y;
            sB[n * 36 + k4 * 4 + 2] = vb.z; sB[n * 36 + k4 * 4 + 3] = vb.w;
        }
        __syncthreads();
        #pragma unroll
        for (int ks = 0; ks < 4; ks++) {
            int kk = ks * 8;
            uint32_t a[2][4];
            #pragma unroll
            for (int mi = 0; mi < 2; mi++) {
                const float* ap  = &sA[(kk + t) * 72 + mw + mi * 16];
                const float* ap2 = &sA[(kk + t + 4) * 72 + mw + mi * 16];
                a[mi][0] = __float_as_uint(ap[g]);
                a[mi][1] = __float_as_uint(ap[g + 8]);
                a[mi][2] = __float_as_uint(ap2[g]);
                a[mi][3] = __float_as_uint(ap2[g + 8]);
            }
            #pragma unroll
            for (int nj = 0; nj < 2; nj++) {
                const float* bp = &sB[(nw + nj * 8 + g) * 36 + kk];
                uint32_t b0 = __float_as_uint(bp[t]);
                uint32_t b1 = __float_as_uint(bp[t + 4]);
                mma_tf32(acc[0][nj], a[0], b0, b1);
                mma_tf32(acc[1][nj], a[1], b0, b1);
            }
        }
        __syncthreads();
    }
}

// ---------------- Kernel 2: QKV projection ----------------
__global__ void __launch_bounds__(256) proj_qkv_kernel(
    const float* __restrict__ bq, const float* __restrict__ bk, const float* __restrict__ bv) {
    __shared__ float sA[32 * 72];
    __shared__ float sB[64 * 36];
    int z = blockIdx.z;
    const float* bias = z == 0 ? bq : (z == 1 ? bk : bv);
    float* out = g_qkvh[z];
    int m0 = blockIdx.x * 64, n0 = blockIdx.y * 64;

    float4 acc[2][2];
    gemm_tile_tf32(g_xn[z], g_wt[z], m0, n0, acc, sA, sB);

    int lane = threadIdx.x & 31, w = threadIdx.x >> 5;
    int g = lane >> 2, t = lane & 3;
    int wm = w >> 2, wn = w & 3;
    #pragma unroll
    for (int mi = 0; mi < 2; mi++) {
        #pragma unroll
        for (int nj = 0; nj < 2; nj++) {
            int n = n0 + wn * 16 + nj * 8 + 2 * t;
            int hh = n >> 6, dd = n & 63;
            float b0 = bias[n], b1 = bias[n + 1];
            #pragma unroll
            for (int r = 0; r < 2; r++) {
                int m = m0 + wm * 32 + mi * 16 + g + r * 8;
                int bidx = m >> 11, srow = m & 2047;
                float2 val;
                if (r == 0) { val.x = acc[mi][nj].x + b0; val.y = acc[mi][nj].y + b1; }
                else        { val.x = acc[mi][nj].z + b0; val.y = acc[mi][nj].w + b1; }
                val.x = rnd_tf32(val.x); val.y = rnd_tf32(val.y);
                *(float2*)&out[(((size_t)(bidx * Hh + hh) * Ss + srow) * DK) + dd] = val;
            }
        }
    }
}

// ---------------- Kernel 4: output projection ----------------
__global__ void __launch_bounds__(256) proj_out_kernel(
    const float* __restrict__ bo, const float* __restrict__ ls, float* __restrict__ Cout) {
    __shared__ float sA[32 * 72];
    __shared__ float sB[64 * 36];
    int m0 = blockIdx.x * 64, n0 = blockIdx.y * 64;

    float4 acc[2][2];
    gemm_tile_tf32(g_x, g_wt[3], m0, n0, acc, sA, sB);

    int lane = threadIdx.x & 31, w = threadIdx.x >> 5;
    int g = lane >> 2, t = lane & 3;
    int wm = w >> 2, wn = w & 3;
    #pragma unroll
    for (int mi = 0; mi < 2; mi++) {
        #pragma unroll
        for (int nj = 0; nj < 2; nj++) {
            int n = n0 + wn * 16 + nj * 8 + 2 * t;
            float b0 = bo[n], b1 = bo[n + 1];
            float l0 = ls[n], l1 = ls[n + 1];
            #pragma unroll
            for (int r = 0; r < 2; r++) {
                int m = m0 + wm * 32 + mi * 16 + g + r * 8;
                float2 val;
                if (r == 0) { val.x = (acc[mi][nj].x + b0) * l0; val.y = (acc[mi][nj].y + b1) * l1; }
                else        { val.x = (acc[mi][nj].z + b0) * l0; val.y = (acc[mi][nj].w + b1) * l1; }
                *(float2*)&Cout[(size_t)m * Dd + n] = val;
            }
        }
    }
}

// ---------------- Kernel 3: attention — barrier-free streaming, register P ----------------
// 512 threads = 16 warps. Warp w owns keys kt*128 + w*8 .. +7 for each of 16 tiles.
// P held in registers (16 float4 mma C-fragments). K/V streamed from L2 by LDG
// directly into mma fragments. Smem only for row-sum exchange + final PV reduction.
#define TQ 16
#define FULLM 0xFFFFFFFFu

__global__ void __launch_bounds__(512, 1) attn_kernel(float* __restrict__ d_out) {
    __shared__ float sred[16 * 18];     // [warp][row] row-sum partials
    __shared__ float sinv[16];          // per-row 1/sum
    __shared__ float sacc[8 * 1024];    // 32KB staging for PV reduction tree

    int qt = blockIdx.x, h = blockIdx.y, b = blockIdx.z;
    const float* Q = g_qkvh[0] + (size_t)(b * Hh + h) * Ss * DK;
    const float* K = g_qkvh[1] + (size_t)(b * Hh + h) * Ss * DK;
    const float* V = g_qkvh[2] + (size_t)(b * Hh + h) * Ss * DK;
    float* attn_out = d_out + (size_t)BS * Dd
                    + ((size_t)((b * Hh + h) * Ss) + (size_t)qt * TQ) * Ss;

    int tid = threadIdx.x;
    int lane = tid & 31, w = tid >> 5;
    int g = lane >> 2, t = lane & 3;
    int q0 = qt * TQ;

    // Q fragments straight from gmem (L2-resident, tf32-rounded at store)
    uint32_t qa[8][4];
    {
        const float* Qb = Q + (size_t)q0 * DK;
        #pragma unroll
        for (int ks = 0; ks < 8; ks++) {
            int c = ks * 8 + t;
            qa[ks][0] = __float_as_uint(Qb[g * DK + c]);
            qa[ks][1] = __float_as_uint(Qb[(g + 8) * DK + c]);
            qa[ks][2] = __float_as_uint(Qb[g * DK + c + 4]);
            qa[ks][3] = __float_as_uint(Qb[(g + 8) * DK + c + 4]);
        }
    }

    const float scale = 0.125f;
    float4 p[16];
    float2 rsum = make_float2(0.f, 0.f);

    // ---- QK^T + bias + exp, fully in registers; K streamed by LDG ----
    #pragma unroll 1
    for (int kt = 0; kt < 16; kt++) {
        const float* Kb = K + (size_t)(kt * 128 + w * 8) * DK;
        float4 acc = make_float4(0.f, 0.f, 0.f, 0.f);
        #pragma unroll
        for (int ks = 0; ks < 8; ks++) {
            float kv0 = Kb[g * DK + ks * 8 + t];
            float kv1 = Kb[g * DK + ks * 8 + t + 4];
            mma_tf32(acc, qa[ks], __float_as_uint(kv0), __float_as_uint(kv1));
        }
        int gk = kt * 128 + w * 8 + 2 * t;
        float2 b0 = *(const float2*)&g_bias[(size_t)(q0 + g) * Ss + gk];
        float2 b1 = *(const float2*)&g_bias[(size_t)(q0 + g + 8) * Ss + gk];
        float4 pv;
        pv.x = fast_exp(fmaf(acc.x, scale, b0.x));
        pv.y = fast_exp(fmaf(acc.y, scale, b0.y));
        pv.z = fast_exp(fmaf(acc.z, scale, b1.x));
        pv.w = fast_exp(fmaf(acc.w, scale, b1.y));
        p[kt] = pv;
        rsum.x += pv.x + pv.y;
        rsum.y += pv.z + pv.w;
    }

    // ---- row-sum reduction: lanes (t) then warps via smem ----
    rsum.x += __shfl_xor_sync(FULLM, rsum.x, 1);
    rsum.x += __shfl_xor_sync(FULLM, rsum.x, 2);
    rsum.y += __shfl_xor_sync(FULLM, rsum.y, 1);
    rsum.y += __shfl_xor_sync(FULLM, rsum.y, 2);
    if (t == 0) {
        sred[w * 18 + g] = rsum.x;
        sred[w * 18 + 8 + g] = rsum.y;
    }
    __syncthreads();
    {
        // warp r (0..15) sums row r over 16 warp-partials
        float v = (lane < 16) ? sred[lane * 18 + w] : 0.f;
        #pragma unroll
        for (int o = 8; o; o >>= 1) v += __shfl_xor_sync(FULLM, v, o);
        if (lane == 0) sinv[w] = 1.f / v;
    }
    __syncthreads();
    float invx = sinv[g], invy = sinv[8 + g];

    // ---- normalize, write attn to gmem (exact), round P for mma ----
    #pragma unroll
    for (int kt = 0; kt < 16; kt++) {
        float4 pv = p[kt];
        pv.x *= invx; pv.y *= invx; pv.z *= invy; pv.w *= invy;
        int gk = kt * 128 + w * 8 + 2 * t;
        *(float2*)&attn_out[(size_t)g * Ss + gk] = make_float2(pv.x, pv.y);
        *(float2*)&attn_out[(size_t)(g + 8) * Ss + gk] = make_float2(pv.z, pv.w);
        pv.x = rnd_tf32(pv.x); pv.y = rnd_tf32(pv.y);
        pv.z = rnd_tf32(pv.z); pv.w = rnd_tf32(pv.w);
        p[kt] = pv;
    }

    // ---- PV: per-warp partial over its keys; V streamed by LDG; A-frags via shuffle ----
    float4 oacc[8];
    #pragma unroll
    for (int j = 0; j < 8; j++) oacc[j] = make_float4(0.f, 0.f, 0.f, 0.f);

    #pragma unroll 1
    for (int kt = 0; kt < 16; kt++) {
        float4 pk = p[kt];
        int src  = (g << 2) + (t >> 1);
        int src2 = src + 2;
        float lo, hi;
        uint32_t A[4];
        lo = __shfl_sync(FULLM, pk.x, src);  hi = __shfl_sync(FULLM, pk.y, src);
        A[0] = __float_as_uint((t & 1) ? hi : lo);
        lo = __shfl_sync(FULLM, pk.z, src);  hi = __shfl_sync(FULLM, pk.w, src);
        A[1] = __float_as_uint((t & 1) ? hi : lo);
        lo = __shfl_sync(FULLM, pk.x, src2); hi = __shfl_sync(FULLM, pk.y, src2);
        A[2] = __float_as_uint((t & 1) ? hi : lo);
        lo = __shfl_sync(FULLM, pk.z, src2); hi = __shfl_sync(FULLM, pk.w, src2);
        A[3] = __float_as_uint((t & 1) ? hi : lo);

        const float* Vb = V + (size_t)(kt * 128 + w * 8) * DK;
        #pragma unroll
        for (int j = 0; j < 8; j++) {
            float v0 = Vb[t * DK + j * 8 + g];
            float v1 = Vb[(t + 4) * DK + j * 8 + g];
            mma_tf32(oacc[j], A, __float_as_uint(v0), __float_as_uint(v1));
        }
    }

    // ---- reduction tree across 16 warps (4 steps) ----
    // Each warp region: 8 accumulators x 128 floats = 1024 floats. Stride per j = 128.
    #pragma unroll
    for (int step = 8; step >= 1; step >>= 1) {
        __syncthreads();
        if (w >= step && w < 2 * step) {
            float* dst = &sacc[(w - step) * 1024 + lane * 4];
            #pragma unroll
            for (int j = 0; j < 8; j++) *(float4*)&dst[j * 128] = oacc[j];
        }
        __syncthreads();
        if (w < step) {
            const float* srcp = &sacc[w * 1024 + lane * 4];
            #pragma unroll
            for (int j = 0; j < 8; j++) {
                float4 o2 = *(const float4*)&srcp[j * 128];
                oacc[j].x += o2.x; oacc[j].y += o2.y;
                oacc[j].z += o2.z; oacc[j].w += o2.w;
            }
        }
    }

    if (w == 0) {
        #pragma unroll
        for (int j = 0; j < 8; j++) {
            int col = h * DK + j * 8 + 2 * t;
            float2 r0, r1;
            r0.x = rnd_tf32(oacc[j].x); r0.y = rnd_tf32(oacc[j].y);
            r1.x = rnd_tf32(oacc[j].z); r1.y = rnd_tf32(oacc[j].w);
            *(float2*)&g_x[((size_t)(b * Ss + q0 + g)) * Dd + col] = r0;
            *(float2*)&g_x[((size_t)(b * Ss + q0 + g + 8)) * Dd + col] = r1;
        }
    }
}

// ---------------- launch ----------------
extern "C" void kernel_launch(void* const* d_in, const int* in_sizes, int n_in,
                              void* d_out, int out_size) {
    const float* q    = (const float*)d_in[0];
    const float* k    = (const float*)d_in[1];
    const float* v    = (const float*)d_in[2];
    const int*   mask = (const int*)  d_in[3];
    const float* pos  = (const float*)d_in[4];
    const float* ln_g = (const float*)d_in[5];
    const float* ln_b = (const float*)d_in[6];
    const float* wq   = (const float*)d_in[7];
    const float* bq   = (const float*)d_in[8];
    const float* wk   = (const float*)d_in[9];
    const float* bk   = (const float*)d_in[10];
    const float* wv   = (const float*)d_in[11];
    const float* bv   = (const float*)d_in[12];
    const float* wo   = (const float*)d_in[13];
    const float* bo   = (const float*)d_in[14];
    const float* ls   = (const float*)d_in[15];
    float* out = (float*)d_out;

    bias_kernel<<<(Ss * (size_t)Ss) / 4096, 1024>>>(pos, mask);
    ln_kernel<<<dim3(BS, 3), 256>>>(q, k, v, ln_g, ln_b);
    wt_kernel<<<dim3(16, 16, 4), 256>>>(wq, wk, wv, wo);
    proj_qkv_kernel<<<dim3(BS / 64, Dd / 64, 3), 256>>>(bq, bk, bv);
    attn_kernel<<<dim3(Ss / TQ, Hh, Bb), 512>>>(out);
    proj_out_kernel<<<dim3(BS / 64, Dd / 64), 256>>>(bo, ls, out);
}

// round 7
// speedup vs baseline: 3.6161x; 1.2692x over previous
#include <cuda_runtime.h>
#include <math.h>
#include <stdint.h>

#define Bb 4
#define Ss 2048
#define Dd 512
#define Hh 8
#define DK 64
#define BS (Bb*Ss)          // 8192 rows
#define LN_EPS 1e-5f
#define NEG_BIG (-1e30f)

// ---------------- scratch (static device globals; no allocation) ----------------
__device__ float g_xn[3][(size_t)BS*Dd];                 // normalized q,k,v (tf32-rounded)
__device__ float g_qkvh[3][(size_t)Bb*Hh*Ss*DK];         // head-major Q,V (tf32) [1] unused
__device__ float g_kt[(size_t)Bb*Hh*DK*Ss];              // K transposed per (b,h): [d][key]
__device__ float g_x[(size_t)BS*Dd];                     // attention output (tf32-rounded)
__device__ float g_wt[4][(size_t)Dd*Dd];                 // W^T, tf32-rounded: [n][k]
__device__ float g_bias[(size_t)Ss*Ss];                  // mask? pos : -1e30  (16.8 MB)

// ---------------- helpers ----------------
__device__ __forceinline__ uint32_t f2tf32(float x) {
    uint32_t r;
    asm volatile("cvt.rna.tf32.f32 %0, %1;" : "=r"(r) : "f"(x));
    return r;
}
__device__ __forceinline__ float rnd_tf32(float x) { return __uint_as_float(f2tf32(x)); }

__device__ __forceinline__ void mma_tf32(float4& d, const uint32_t a[4],
                                         uint32_t b0, uint32_t b1) {
    asm volatile(
        "mma.sync.aligned.m16n8k8.row.col.f32.tf32.tf32.f32 "
        "{%0,%1,%2,%3}, {%4,%5,%6,%7}, {%8,%9}, {%0,%1,%2,%3};\n"
        : "+f"(d.x), "+f"(d.y), "+f"(d.z), "+f"(d.w)
        : "r"(a[0]), "r"(a[1]), "r"(a[2]), "r"(a[3]), "r"(b0), "r"(b1));
}

__device__ __forceinline__ void cpa16(float* s, const float* g) {
    uint32_t sa = (uint32_t)__cvta_generic_to_shared(s);
    asm volatile("cp.async.ca.shared.global [%0], [%1], 16;\n" :: "r"(sa), "l"(g));
}
#define CP_COMMIT() asm volatile("cp.async.commit_group;\n")
template<int N> __device__ __forceinline__ void cp_wait() {
    asm volatile("cp.async.wait_group %0;\n" :: "n"(N));
}

// FMA-pipe exp; safe for any x (clamped below), ~1e-7 rel err.
__device__ __forceinline__ float fast_exp(float x) {
    x = fmaxf(x, -87.0f);
    float t = x * 1.4426950408889634f;
    float z = t + 12582912.0f;
    float f = t - (z - 12582912.0f);
    int   e = __float_as_int(z) - 0x4B400000;
    float p = 1.33335581e-3f;
    p = fmaf(p, f, 9.61812910e-3f);
    p = fmaf(p, f, 5.55041087e-2f);
    p = fmaf(p, f, 2.40226507e-1f);
    p = fmaf(p, f, 6.93147180e-1f);
    p = fmaf(p, f, 1.0f);
    return __int_as_float((e + 127) << 23) * p;
}

// ---------------- Kernel 0: fuse mask+pos into additive bias ----------------
__global__ void bias_kernel(const float* __restrict__ pos, const int* __restrict__ mask) {
    size_t i = (size_t)blockIdx.x * 1024 + threadIdx.x;
    float4 p = *(const float4*)&pos[i * 4];
    int4   m = *(const int4*)&mask[i * 4];
    float4 o;
    o.x = m.x ? p.x : NEG_BIG;
    o.y = m.y ? p.y : NEG_BIG;
    o.z = m.z ? p.z : NEG_BIG;
    o.w = m.w ? p.w : NEG_BIG;
    *(float4*)&g_bias[i * 4] = o;
}

// ---------------- Kernel 1: LayerNorm (tf32-rounded output) ----------------
__global__ void ln_kernel(const float* __restrict__ q, const float* __restrict__ k,
                          const float* __restrict__ v, const float* __restrict__ g,
                          const float* __restrict__ b) {
    int row = blockIdx.x;
    int which = blockIdx.y;
    const float* xs = which == 0 ? q : (which == 1 ? k : v);
    const float* x = xs + (size_t)row * Dd;
    float* y = g_xn[which] + (size_t)row * Dd;
    int t = threadIdx.x;

    float v0 = x[t], v1 = x[t + 256];
    float s = v0 + v1, s2 = v0 * v0 + v1 * v1;

    __shared__ float rs[8], rs2[8];
    #pragma unroll
    for (int o = 16; o; o >>= 1) {
        s  += __shfl_xor_sync(0xFFFFFFFFu, s,  o);
        s2 += __shfl_xor_sync(0xFFFFFFFFu, s2, o);
    }
    if ((t & 31) == 0) { rs[t >> 5] = s; rs2[t >> 5] = s2; }
    __syncthreads();
    __shared__ float smu, sinv;
    if (t == 0) {
        float S = 0.f, S2 = 0.f;
        #pragma unroll
        for (int i = 0; i < 8; i++) { S += rs[i]; S2 += rs2[i]; }
        float mu = S * (1.f / 512.f);
        float var = S2 * (1.f / 512.f) - mu * mu;
        smu = mu; sinv = rsqrtf(var + LN_EPS);
    }
    __syncthreads();
    float mu = smu, inv = sinv;
    y[t]       = rnd_tf32((v0 - mu) * inv * g[t]       + b[t]);
    y[t + 256] = rnd_tf32((v1 - mu) * inv * g[t + 256] + b[t + 256]);
}

// ---------------- Kernel 1b: weight transpose + tf32 round ----------------
__global__ void wt_kernel(const float* __restrict__ wq, const float* __restrict__ wk,
                          const float* __restrict__ wv, const float* __restrict__ wo) {
    __shared__ float tile[32][33];
    int z = blockIdx.z;
    const float* W = z == 0 ? wq : (z == 1 ? wk : (z == 2 ? wv : wo));
    int k0 = blockIdx.x * 32, n0 = blockIdx.y * 32;
    int c = threadIdx.x & 31, r0 = threadIdx.x >> 5;
    #pragma unroll
    for (int i = 0; i < 4; i++) {
        int r = r0 + i * 8;
        tile[r][c] = W[(size_t)(k0 + r) * Dd + n0 + c];
    }
    __syncthreads();
    #pragma unroll
    for (int i = 0; i < 4; i++) {
        int r = r0 + i * 8;
        g_wt[z][(size_t)(n0 + r) * Dd + k0 + c] = rnd_tf32(tile[c][r]);
    }
}

// ---------------- tf32 GEMM tile core (BM=64, BN=64, BK=32, cp.async 2-stage) ----------------
// A: [M][512] row-major; Bt: [n][k]. Smem tiles row-major, row stride 36 (144B, 16B-aligned).
#define GSTG 2304   // one stage: 64 rows * 36

__device__ __forceinline__ void gemm_load_stage(
    const float* __restrict__ A, const float* __restrict__ Bt,
    int m0, int n0, int k0, float* sA, float* sB) {
    int tid = threadIdx.x;
    #pragma unroll
    for (int i = 0; i < 2; i++) {
        int idx = tid + i * 256;            // 512 chunks = 64 rows x 8
        int m = idx >> 3, c = idx & 7;
        cpa16(&sA[m * 36 + c * 4], &A[(size_t)(m0 + m) * Dd + k0 + c * 4]);
    }
    #pragma unroll
    for (int i = 0; i < 2; i++) {
        int idx = tid + i * 256;
        int n = idx >> 3, c = idx & 7;
        cpa16(&sB[n * 36 + c * 4], &Bt[(size_t)(n0 + n) * Dd + k0 + c * 4]);
    }
}

__device__ __forceinline__ void gemm_tile_tf32(
    const float* __restrict__ A, const float* __restrict__ Bt,
    int m0, int n0, float4 acc[2][2], float* sA, float* sB) {
    int tid = threadIdx.x;
    int lane = tid & 31, w = tid >> 5;
    int g = lane >> 2, t = lane & 3;
    int wm = w >> 2, wn = w & 3;
    #pragma unroll
    for (int i = 0; i < 2; i++)
        #pragma unroll
        for (int j = 0; j < 2; j++) acc[i][j] = make_float4(0.f, 0.f, 0.f, 0.f);

    gemm_load_stage(A, Bt, m0, n0, 0, sA, sB);
    CP_COMMIT();

    for (int it = 0; it < 16; it++) {
        if (it < 15) {
            int s = (it + 1) & 1;
            gemm_load_stage(A, Bt, m0, n0, (it + 1) * 32, sA + s * GSTG, sB + s * GSTG);
            CP_COMMIT();
            cp_wait<1>();
        } else {
            cp_wait<0>();
        }
        __syncthreads();

        const float* cA = sA + (it & 1) * GSTG;
        const float* cB = sB + (it & 1) * GSTG;
        #pragma unroll
        for (int ks = 0; ks < 4; ks++) {
            int kk = ks * 8;
            uint32_t a[2][4];
            #pragma unroll
            for (int mi = 0; mi < 2; mi++) {
                const float* ap = &cA[(wm * 32 + mi * 16 + g) * 36 + kk + t];
                a[mi][0] = __float_as_uint(ap[0]);
                a[mi][1] = __float_as_uint(ap[8 * 36]);
                a[mi][2] = __float_as_uint(ap[4]);
                a[mi][3] = __float_as_uint(ap[8 * 36 + 4]);
            }
            #pragma unroll
            for (int nj = 0; nj < 2; nj++) {
                const float* bp = &cB[(wn * 16 + nj * 8 + g) * 36 + kk];
                uint32_t b0 = __float_as_uint(bp[t]);
                uint32_t b1 = __float_as_uint(bp[t + 4]);
                mma_tf32(acc[0][nj], a[0], b0, b1);
                mma_tf32(acc[1][nj], a[1], b0, b1);
            }
        }
        __syncthreads();
    }
}

// ---------------- Kernel 2: QKV projection (K written transposed) ----------------
__global__ void __launch_bounds__(256) proj_qkv_kernel(
    const float* __restrict__ bq, const float* __restrict__ bk, const float* __restrict__ bv) {
    __shared__ float sA[2 * GSTG];
    __shared__ float sB[2 * GSTG];
    int z = blockIdx.z;
    const float* bias = z == 0 ? bq : (z == 1 ? bk : bv);
    int m0 = blockIdx.x * 64, n0 = blockIdx.y * 64;

    float4 acc[2][2];
    gemm_tile_tf32(g_xn[z], g_wt[z], m0, n0, acc, sA, sB);

    int lane = threadIdx.x & 31, w = threadIdx.x >> 5;
    int g = lane >> 2, t = lane & 3;
    int wm = w >> 2, wn = w & 3;
    #pragma unroll
    for (int mi = 0; mi < 2; mi++) {
        #pragma unroll
        for (int nj = 0; nj < 2; nj++) {
            int n = n0 + wn * 16 + nj * 8 + 2 * t;
            int hh = n >> 6, dd = n & 63;
            float b0 = bias[n], b1 = bias[n + 1];
            #pragma unroll
            for (int r = 0; r < 2; r++) {
                int m = m0 + wm * 32 + mi * 16 + g + r * 8;
                int bidx = m >> 11, srow = m & 2047;
                float2 val;
                if (r == 0) { val.x = acc[mi][nj].x + b0; val.y = acc[mi][nj].y + b1; }
                else        { val.x = acc[mi][nj].z + b0; val.y = acc[mi][nj].w + b1; }
                val.x = rnd_tf32(val.x); val.y = rnd_tf32(val.y);
                if (z == 1) {
                    // K transposed: KT[(bh)*64 + d][key]
                    float* KT = g_kt + (size_t)(bidx * Hh + hh) * DK * Ss;
                    KT[(size_t)dd * Ss + srow]       = val.x;
                    KT[(size_t)(dd + 1) * Ss + srow] = val.y;
                } else {
                    float* out = g_qkvh[z];
                    *(float2*)&out[(((size_t)(bidx * Hh + hh) * Ss + srow) * DK) + dd] = val;
                }
            }
        }
    }
}

// ---------------- Kernel 4: output projection ----------------
__global__ void __launch_bounds__(256) proj_out_kernel(
    const float* __restrict__ bo, const float* __restrict__ ls, float* __restrict__ Cout) {
    __shared__ float sA[2 * GSTG];
    __shared__ float sB[2 * GSTG];
    int m0 = blockIdx.x * 64, n0 = blockIdx.y * 64;

    float4 acc[2][2];
    gemm_tile_tf32(g_x, g_wt[3], m0, n0, acc, sA, sB);

    int lane = threadIdx.x & 31, w = threadIdx.x >> 5;
    int g = lane >> 2, t = lane & 3;
    int wm = w >> 2, wn = w & 3;
    #pragma unroll
    for (int mi = 0; mi < 2; mi++) {
        #pragma unroll
        for (int nj = 0; nj < 2; nj++) {
            int n = n0 + wn * 16 + nj * 8 + 2 * t;
            float b0 = bo[n], b1 = bo[n + 1];
            float l0 = ls[n], l1 = ls[n + 1];
            #pragma unroll
            for (int r = 0; r < 2; r++) {
                int m = m0 + wm * 32 + mi * 16 + g + r * 8;
                float2 val;
                if (r == 0) { val.x = (acc[mi][nj].x + b0) * l0; val.y = (acc[mi][nj].y + b1) * l1; }
                else        { val.x = (acc[mi][nj].z + b0) * l0; val.y = (acc[mi][nj].w + b1) * l1; }
                *(float2*)&Cout[(size_t)m * Dd + n] = val;
            }
        }
    }
}

// ---------------- Kernel 3: attention — streaming, register P, transposed K ----------------
#define TQ 16
#define FULLM 0xFFFFFFFFu

__global__ void __launch_bounds__(512, 1) attn_kernel(float* __restrict__ d_out) {
    __shared__ float sred[16 * 18];
    __shared__ float sinv[16];
    __shared__ float sacc[8 * 1024];

    int qt = blockIdx.x, h = blockIdx.y, b = blockIdx.z;
    const float* Q  = g_qkvh[0] + (size_t)(b * Hh + h) * Ss * DK;
    const float* KT = g_kt      + (size_t)(b * Hh + h) * DK * Ss;
    const float* V  = g_qkvh[2] + (size_t)(b * Hh + h) * Ss * DK;
    float* attn_out = d_out + (size_t)BS * Dd
                    + ((size_t)((b * Hh + h) * Ss) + (size_t)qt * TQ) * Ss;

    int tid = threadIdx.x;
    int lane = tid & 31, w = tid >> 5;
    int g = lane >> 2, t = lane & 3;
    int q0 = qt * TQ;

    // Q fragments straight from gmem (L2-resident, tf32-rounded at store)
    uint32_t qa[8][4];
    {
        const float* Qb = Q + (size_t)q0 * DK;
        #pragma unroll
        for (int ks = 0; ks < 8; ks++) {
            int c = ks * 8 + t;
            qa[ks][0] = __float_as_uint(Qb[g * DK + c]);
            qa[ks][1] = __float_as_uint(Qb[(g + 8) * DK + c]);
            qa[ks][2] = __float_as_uint(Qb[g * DK + c + 4]);
            qa[ks][3] = __float_as_uint(Qb[(g + 8) * DK + c + 4]);
        }
    }

    const float scale = 0.125f;
    float4 p[16];
    float2 rsum = make_float2(0.f, 0.f);

    // ---- QK^T + bias + exp; K^T streamed by coalesced LDG (4 lines, full sectors) ----
    #pragma unroll 1
    for (int kt = 0; kt < 16; kt++) {
        int colb = kt * 128 + w * 8 + g;       // per-lane key column
        float4 acc = make_float4(0.f, 0.f, 0.f, 0.f);
        #pragma unroll
        for (int ks = 0; ks < 8; ks++) {
            float kv0 = KT[(size_t)(ks * 8 + t) * Ss + colb];
            float kv1 = KT[(size_t)(ks * 8 + t + 4) * Ss + colb];
            mma_tf32(acc, qa[ks], __float_as_uint(kv0), __float_as_uint(kv1));
        }
        int gk = kt * 128 + w * 8 + 2 * t;
        float2 b0 = *(const float2*)&g_bias[(size_t)(q0 + g) * Ss + gk];
        float2 b1 = *(const float2*)&g_bias[(size_t)(q0 + g + 8) * Ss + gk];
        float4 pv;
        pv.x = fast_exp(fmaf(acc.x, scale, b0.x));
        pv.y = fast_exp(fmaf(acc.y, scale, b0.y));
        pv.z = fast_exp(fmaf(acc.z, scale, b1.x));
        pv.w = fast_exp(fmaf(acc.w, scale, b1.y));
        p[kt] = pv;
        rsum.x += pv.x + pv.y;
        rsum.y += pv.z + pv.w;
    }

    // ---- row-sum reduction ----
    rsum.x += __shfl_xor_sync(FULLM, rsum.x, 1);
    rsum.x += __shfl_xor_sync(FULLM, rsum.x, 2);
    rsum.y += __shfl_xor_sync(FULLM, rsum.y, 1);
    rsum.y += __shfl_xor_sync(FULLM, rsum.y, 2);
    if (t == 0) {
        sred[w * 18 + g] = rsum.x;
        sred[w * 18 + 8 + g] = rsum.y;
    }
    __syncthreads();
    {
        float v = (lane < 16) ? sred[lane * 18 + w] : 0.f;
        #pragma unroll
        for (int o = 8; o; o >>= 1) v += __shfl_xor_sync(FULLM, v, o);
        if (lane == 0) sinv[w] = 1.f / v;
    }
    __syncthreads();
    float invx = sinv[g], invy = sinv[8 + g];

    // ---- normalize, write attn (exact), round P for mma ----
    #pragma unroll
    for (int kt = 0; kt < 16; kt++) {
        float4 pv = p[kt];
        pv.x *= invx; pv.y *= invx; pv.z *= invy; pv.w *= invy;
        int gk = kt * 128 + w * 8 + 2 * t;
        *(float2*)&attn_out[(size_t)g * Ss + gk] = make_float2(pv.x, pv.y);
        *(float2*)&attn_out[(size_t)(g + 8) * Ss + gk] = make_float2(pv.z, pv.w);
        pv.x = rnd_tf32(pv.x); pv.y = rnd_tf32(pv.y);
        pv.z = rnd_tf32(pv.z); pv.w = rnd_tf32(pv.w);
        p[kt] = pv;
    }

    // ---- PV: per-warp partial; V streamed by LDG (4 lines, full sectors) ----
    float4 oacc[8];
    #pragma unroll
    for (int j = 0; j < 8; j++) oacc[j] = make_float4(0.f, 0.f, 0.f, 0.f);

    #pragma unroll 1
    for (int kt = 0; kt < 16; kt++) {
        float4 pk = p[kt];
        int src  = (g << 2) + (t >> 1);
        int src2 = src + 2;
        float lo, hi;
        uint32_t A[4];
        lo = __shfl_sync(FULLM, pk.x, src);  hi = __shfl_sync(FULLM, pk.y, src);
        A[0] = __float_as_uint((t & 1) ? hi : lo);
        lo = __shfl_sync(FULLM, pk.z, src);  hi = __shfl_sync(FULLM, pk.w, src);
        A[1] = __float_as_uint((t & 1) ? hi : lo);
        lo = __shfl_sync(FULLM, pk.x, src2); hi = __shfl_sync(FULLM, pk.y, src2);
        A[2] = __float_as_uint((t & 1) ? hi : lo);
        lo = __shfl_sync(FULLM, pk.z, src2); hi = __shfl_sync(FULLM, pk.w, src2);
        A[3] = __float_as_uint((t & 1) ? hi : lo);

        const float* Vb = V + (size_t)(kt * 128 + w * 8) * DK;
        #pragma unroll
        for (int j = 0; j < 8; j++) {
            float v0 = Vb[t * DK + j * 8 + g];
            float v1 = Vb[(t + 4) * DK + j * 8 + g];
            mma_tf32(oacc[j], A, __float_as_uint(v0), __float_as_uint(v1));
        }
    }

    // ---- reduction tree across 16 warps ----
    #pragma unroll
    for (int step = 8; step >= 1; step >>= 1) {
        __syncthreads();
        if (w >= step && w < 2 * step) {
            float* dst = &sacc[(w - step) * 1024 + lane * 4];
            #pragma unroll
            for (int j = 0; j < 8; j++) *(float4*)&dst[j * 128] = oacc[j];
        }
        __syncthreads();
        if (w < step) {
            const float* srcp = &sacc[w * 1024 + lane * 4];
            #pragma unroll
            for (int j = 0; j < 8; j++) {
                float4 o2 = *(const float4*)&srcp[j * 128];
                oacc[j].x += o2.x; oacc[j].y += o2.y;
                oacc[j].z += o2.z; oacc[j].w += o2.w;
            }
        }
    }

    if (w == 0) {
        #pragma unroll
        for (int j = 0; j < 8; j++) {
            int col = h * DK + j * 8 + 2 * t;
            float2 r0, r1;
            r0.x = rnd_tf32(oacc[j].x); r0.y = rnd_tf32(oacc[j].y);
            r1.x = rnd_tf32(oacc[j].z); r1.y = rnd_tf32(oacc[j].w);
            *(float2*)&g_x[((size_t)(b * Ss + q0 + g)) * Dd + col] = r0;
            *(float2*)&g_x[((size_t)(b * Ss + q0 + g + 8)) * Dd + col] = r1;
        }
    }
}

// ---------------- launch ----------------
extern "C" void kernel_launch(void* const* d_in, const int* in_sizes, int n_in,
                              void* d_out, int out_size) {
    const float* q    = (const float*)d_in[0];
    const float* k    = (const float*)d_in[1];
    const float* v    = (const float*)d_in[2];
    const int*   mask = (const int*)  d_in[3];
    const float* pos  = (const float*)d_in[4];
    const float* ln_g = (const float*)d_in[5];
    const float* ln_b = (const float*)d_in[6];
    const float* wq   = (const float*)d_in[7];
    const float* bq   = (const float*)d_in[8];
    const float* wk   = (const float*)d_in[9];
    const float* bk   = (const float*)d_in[10];
    const float* wv   = (const float*)d_in[11];
    const float* bv   = (const float*)d_in[12];
    const float* wo   = (const float*)d_in[13];
    const float* bo   = (const float*)d_in[14];
    const float* ls   = (const float*)d_in[15];
    float* out = (float*)d_out;

    bias_kernel<<<(Ss * (size_t)Ss) / 4096, 1024>>>(pos, mask);
    ln_kernel<<<dim3(BS, 3), 256>>>(q, k, v, ln_g, ln_b);
    wt_kernel<<<dim3(16, 16, 4), 256>>>(wq, wk, wv, wo);
    proj_qkv_kernel<<<dim3(BS / 64, Dd / 64, 3), 256>>>(bq, bk, bv);
    attn_kernel<<<dim3(Ss / TQ, Hh, Bb), 512>>>(out);
    proj_out_kernel<<<dim3(BS / 64, Dd / 64), 256>>>(bo, ls, out);
}

// round 8
// speedup vs baseline: 4.0926x; 1.1318x over previous
#include <cuda_runtime.h>
#include <math.h>
#include <stdint.h>

#define Bb 4
#define Ss 2048
#define Dd 512
#define Hh 8
#define DK 64
#define BS (Bb*Ss)          // 8192 rows
#define LN_EPS 1e-5f
#define NEG_BIG (-1e30f)

// ---------------- scratch (static device globals; no allocation) ----------------
__device__ float g_xn[3][(size_t)BS*Dd];                 // normalized q,k,v (tf32-rounded)
__device__ float g_qkvh[3][(size_t)Bb*Hh*Ss*DK];         // head-major Q,V (tf32) [1] unused
__device__ float g_kt[(size_t)Bb*Hh*DK*Ss];              // K transposed per (b,h): [d][key]
__device__ float g_x[(size_t)BS*Dd];                     // attention output (tf32-rounded)
__device__ float g_wt[4][(size_t)Dd*Dd];                 // W^T, tf32-rounded: [n][k]
__device__ float g_bias[(size_t)Ss*Ss];                  // mask? pos : -1e30  (16.8 MB)

// ---------------- helpers ----------------
__device__ __forceinline__ uint32_t f2tf32(float x) {
    uint32_t r;
    asm volatile("cvt.rna.tf32.f32 %0, %1;" : "=r"(r) : "f"(x));
    return r;
}
__device__ __forceinline__ float rnd_tf32(float x) { return __uint_as_float(f2tf32(x)); }

__device__ __forceinline__ void mma_tf32(float4& d, const uint32_t a[4],
                                         uint32_t b0, uint32_t b1) {
    asm volatile(
        "mma.sync.aligned.m16n8k8.row.col.f32.tf32.tf32.f32 "
        "{%0,%1,%2,%3}, {%4,%5,%6,%7}, {%8,%9}, {%0,%1,%2,%3};\n"
        : "+f"(d.x), "+f"(d.y), "+f"(d.z), "+f"(d.w)
        : "r"(a[0]), "r"(a[1]), "r"(a[2]), "r"(a[3]), "r"(b0), "r"(b1));
}

__device__ __forceinline__ void cpa16(float* s, const float* g) {
    uint32_t sa = (uint32_t)__cvta_generic_to_shared(s);
    asm volatile("cp.async.ca.shared.global [%0], [%1], 16;\n" :: "r"(sa), "l"(g));
}
#define CP_COMMIT() asm volatile("cp.async.commit_group;\n")
template<int N> __device__ __forceinline__ void cp_wait() {
    asm volatile("cp.async.wait_group %0;\n" :: "n"(N));
}

// FMA-pipe exp; safe for any x (clamped below), ~1e-7 rel err.
__device__ __forceinline__ float fast_exp(float x) {
    x = fmaxf(x, -87.0f);
    float t = x * 1.4426950408889634f;
    float z = t + 12582912.0f;
    float f = t - (z - 12582912.0f);
    int   e = __float_as_int(z) - 0x4B400000;
    float p = 1.33335581e-3f;
    p = fmaf(p, f, 9.61812910e-3f);
    p = fmaf(p, f, 5.55041087e-2f);
    p = fmaf(p, f, 2.40226507e-1f);
    p = fmaf(p, f, 6.93147180e-1f);
    p = fmaf(p, f, 1.0f);
    return __int_as_float((e + 127) << 23) * p;
}

// ---------------- Kernel 0: fuse mask+pos into additive bias ----------------
__global__ void bias_kernel(const float* __restrict__ pos, const int* __restrict__ mask) {
    size_t i = (size_t)blockIdx.x * 1024 + threadIdx.x;
    float4 p = *(const float4*)&pos[i * 4];
    int4   m = *(const int4*)&mask[i * 4];
    float4 o;
    o.x = m.x ? p.x : NEG_BIG;
    o.y = m.y ? p.y : NEG_BIG;
    o.z = m.z ? p.z : NEG_BIG;
    o.w = m.w ? p.w : NEG_BIG;
    *(float4*)&g_bias[i * 4] = o;
}

// ---------------- Kernel 1: LayerNorm (tf32-rounded output) ----------------
__global__ void ln_kernel(const float* __restrict__ q, const float* __restrict__ k,
                          const float* __restrict__ v, const float* __restrict__ g,
                          const float* __restrict__ b) {
    int row = blockIdx.x;
    int which = blockIdx.y;
    const float* xs = which == 0 ? q : (which == 1 ? k : v);
    const float* x = xs + (size_t)row * Dd;
    float* y = g_xn[which] + (size_t)row * Dd;
    int t = threadIdx.x;

    float v0 = x[t], v1 = x[t + 256];
    float s = v0 + v1, s2 = v0 * v0 + v1 * v1;

    __shared__ float rs[8], rs2[8];
    #pragma unroll
    for (int o = 16; o; o >>= 1) {
        s  += __shfl_xor_sync(0xFFFFFFFFu, s,  o);
        s2 += __shfl_xor_sync(0xFFFFFFFFu, s2, o);
    }
    if ((t & 31) == 0) { rs[t >> 5] = s; rs2[t >> 5] = s2; }
    __syncthreads();
    __shared__ float smu, sinv;
    if (t == 0) {
        float S = 0.f, S2 = 0.f;
        #pragma unroll
        for (int i = 0; i < 8; i++) { S += rs[i]; S2 += rs2[i]; }
        float mu = S * (1.f / 512.f);
        float var = S2 * (1.f / 512.f) - mu * mu;
        smu = mu; sinv = rsqrtf(var + LN_EPS);
    }
    __syncthreads();
    float mu = smu, inv = sinv;
    y[t]       = rnd_tf32((v0 - mu) * inv * g[t]       + b[t]);
    y[t + 256] = rnd_tf32((v1 - mu) * inv * g[t + 256] + b[t + 256]);
}

// ---------------- Kernel 1b: weight transpose + tf32 round ----------------
__global__ void wt_kernel(const float* __restrict__ wq, const float* __restrict__ wk,
                          const float* __restrict__ wv, const float* __restrict__ wo) {
    __shared__ float tile[32][33];
    int z = blockIdx.z;
    const float* W = z == 0 ? wq : (z == 1 ? wk : (z == 2 ? wv : wo));
    int k0 = blockIdx.x * 32, n0 = blockIdx.y * 32;
    int c = threadIdx.x & 31, r0 = threadIdx.x >> 5;
    #pragma unroll
    for (int i = 0; i < 4; i++) {
        int r = r0 + i * 8;
        tile[r][c] = W[(size_t)(k0 + r) * Dd + n0 + c];
    }
    __syncthreads();
    #pragma unroll
    for (int i = 0; i < 4; i++) {
        int r = r0 + i * 8;
        g_wt[z][(size_t)(n0 + r) * Dd + k0 + c] = rnd_tf32(tile[c][r]);
    }
}

// ---------------- tf32 GEMM tile core (BM=64, BN=64, BK=32, cp.async 2-stage) ----------------
#define GSTG 2304   // one stage: 64 rows * 36

__device__ __forceinline__ void gemm_load_stage(
    const float* __restrict__ A, const float* __restrict__ Bt,
    int m0, int n0, int k0, float* sA, float* sB) {
    int tid = threadIdx.x;
    #pragma unroll
    for (int i = 0; i < 2; i++) {
        int idx = tid + i * 256;
        int m = idx >> 3, c = idx & 7;
        cpa16(&sA[m * 36 + c * 4], &A[(size_t)(m0 + m) * Dd + k0 + c * 4]);
    }
    #pragma unroll
    for (int i = 0; i < 2; i++) {
        int idx = tid + i * 256;
        int n = idx >> 3, c = idx & 7;
        cpa16(&sB[n * 36 + c * 4], &Bt[(size_t)(n0 + n) * Dd + k0 + c * 4]);
    }
}

__device__ __forceinline__ void gemm_tile_tf32(
    const float* __restrict__ A, const float* __restrict__ Bt,
    int m0, int n0, float4 acc[2][2], float* sA, float* sB) {
    int tid = threadIdx.x;
    int lane = tid & 31, w = tid >> 5;
    int g = lane >> 2, t = lane & 3;
    int wm = w >> 2, wn = w & 3;
    #pragma unroll
    for (int i = 0; i < 2; i++)
        #pragma unroll
        for (int j = 0; j < 2; j++) acc[i][j] = make_float4(0.f, 0.f, 0.f, 0.f);

    gemm_load_stage(A, Bt, m0, n0, 0, sA, sB);
    CP_COMMIT();

    for (int it = 0; it < 16; it++) {
        if (it < 15) {
            int s = (it + 1) & 1;
            gemm_load_stage(A, Bt, m0, n0, (it + 1) * 32, sA + s * GSTG, sB + s * GSTG);
            CP_COMMIT();
            cp_wait<1>();
        } else {
            cp_wait<0>();
        }
        __syncthreads();

        const float* cA = sA + (it & 1) * GSTG;
        const float* cB = sB + (it & 1) * GSTG;
        #pragma unroll
        for (int ks = 0; ks < 4; ks++) {
            int kk = ks * 8;
            uint32_t a[2][4];
            #pragma unroll
            for (int mi = 0; mi < 2; mi++) {
                const float* ap = &cA[(wm * 32 + mi * 16 + g) * 36 + kk + t];
                a[mi][0] = __float_as_uint(ap[0]);
                a[mi][1] = __float_as_uint(ap[8 * 36]);
                a[mi][2] = __float_as_uint(ap[4]);
                a[mi][3] = __float_as_uint(ap[8 * 36 + 4]);
            }
            #pragma unroll
            for (int nj = 0; nj < 2; nj++) {
                const float* bp = &cB[(wn * 16 + nj * 8 + g) * 36 + kk];
                uint32_t b0 = __float_as_uint(bp[t]);
                uint32_t b1 = __float_as_uint(bp[t + 4]);
                mma_tf32(acc[0][nj], a[0], b0, b1);
                mma_tf32(acc[1][nj], a[1], b0, b1);
            }
        }
        __syncthreads();
    }
}

// ---------------- Kernel 2: QKV projection (K written transposed) ----------------
__global__ void __launch_bounds__(256) proj_qkv_kernel(
    const float* __restrict__ bq, const float* __restrict__ bk, const float* __restrict__ bv) {
    __shared__ float sA[2 * GSTG];
    __shared__ float sB[2 * GSTG];
    int z = blockIdx.z;
    const float* bias = z == 0 ? bq : (z == 1 ? bk : bv);
    int m0 = blockIdx.x * 64, n0 = blockIdx.y * 64;

    float4 acc[2][2];
    gemm_tile_tf32(g_xn[z], g_wt[z], m0, n0, acc, sA, sB);

    int lane = threadIdx.x & 31, w = threadIdx.x >> 5;
    int g = lane >> 2, t = lane & 3;
    int wm = w >> 2, wn = w & 3;
    #pragma unroll
    for (int mi = 0; mi < 2; mi++) {
        #pragma unroll
        for (int nj = 0; nj < 2; nj++) {
            int n = n0 + wn * 16 + nj * 8 + 2 * t;
            int hh = n >> 6, dd = n & 63;
            float b0 = bias[n], b1 = bias[n + 1];
            #pragma unroll
            for (int r = 0; r < 2; r++) {
                int m = m0 + wm * 32 + mi * 16 + g + r * 8;
                int bidx = m >> 11, srow = m & 2047;
                float2 val;
                if (r == 0) { val.x = acc[mi][nj].x + b0; val.y = acc[mi][nj].y + b1; }
                else        { val.x = acc[mi][nj].z + b0; val.y = acc[mi][nj].w + b1; }
                val.x = rnd_tf32(val.x); val.y = rnd_tf32(val.y);
                if (z == 1) {
                    float* KT = g_kt + (size_t)(bidx * Hh + hh) * DK * Ss;
                    KT[(size_t)dd * Ss + srow]       = val.x;
                    KT[(size_t)(dd + 1) * Ss + srow] = val.y;
                } else {
                    float* out = g_qkvh[z];
                    *(float2*)&out[(((size_t)(bidx * Hh + hh) * Ss + srow) * DK) + dd] = val;
                }
            }
        }
    }
}

// ---------------- Kernel 4: output projection ----------------
__global__ void __launch_bounds__(256) proj_out_kernel(
    const float* __restrict__ bo, const float* __restrict__ ls, float* __restrict__ Cout) {
    __shared__ float sA[2 * GSTG];
    __shared__ float sB[2 * GSTG];
    int m0 = blockIdx.x * 64, n0 = blockIdx.y * 64;

    float4 acc[2][2];
    gemm_tile_tf32(g_x, g_wt[3], m0, n0, acc, sA, sB);

    int lane = threadIdx.x & 31, w = threadIdx.x >> 5;
    int g = lane >> 2, t = lane & 3;
    int wm = w >> 2, wn = w & 3;
    #pragma unroll
    for (int mi = 0; mi < 2; mi++) {
        #pragma unroll
        for (int nj = 0; nj < 2; nj++) {
            int n = n0 + wn * 16 + nj * 8 + 2 * t;
            float b0 = bo[n], b1 = bo[n + 1];
            float l0 = ls[n], l1 = ls[n + 1];
            #pragma unroll
            for (int r = 0; r < 2; r++) {
                int m = m0 + wm * 32 + mi * 16 + g + r * 8;
                float2 val;
                if (r == 0) { val.x = (acc[mi][nj].x + b0) * l0; val.y = (acc[mi][nj].y + b1) * l1; }
                else        { val.x = (acc[mi][nj].z + b0) * l0; val.y = (acc[mi][nj].w + b1) * l1; }
                *(float2*)&Cout[(size_t)m * Dd + n] = val;
            }
        }
    }
}

// ---------------- Kernel 3: attention — streaming, FULLY register-resident P ----------------
// All loops touching p[] are fully unrolled: constant indices => register promotion.
#define TQ 16
#define FULLM 0xFFFFFFFFu

__global__ void __launch_bounds__(512, 1) attn_kernel(float* __restrict__ d_out) {
    __shared__ float sred[16 * 18];
    __shared__ float sinv[16];
    __shared__ float sacc[8 * 1024];

    int qt = blockIdx.x, h = blockIdx.y, b = blockIdx.z;
    const float* Q  = g_qkvh[0] + (size_t)(b * Hh + h) * Ss * DK;
    const float* KT = g_kt      + (size_t)(b * Hh + h) * DK * Ss;
    const float* V  = g_qkvh[2] + (size_t)(b * Hh + h) * Ss * DK;
    float* attn_out = d_out + (size_t)BS * Dd
                    + ((size_t)((b * Hh + h) * Ss) + (size_t)qt * TQ) * Ss;

    int tid = threadIdx.x;
    int lane = tid & 31, w = tid >> 5;
    int g = lane >> 2, t = lane & 3;
    int q0 = qt * TQ;

    // Q fragments straight from gmem (L2-resident, tf32-rounded at store)
    uint32_t qa[8][4];
    {
        const float* Qb = Q + (size_t)q0 * DK;
        #pragma unroll
        for (int ks = 0; ks < 8; ks++) {
            int c = ks * 8 + t;
            qa[ks][0] = __float_as_uint(Qb[g * DK + c]);
            qa[ks][1] = __float_as_uint(Qb[(g + 8) * DK + c]);
            qa[ks][2] = __float_as_uint(Qb[g * DK + c + 4]);
            qa[ks][3] = __float_as_uint(Qb[(g + 8) * DK + c + 4]);
        }
    }

    const float scale = 0.125f;
    float4 p[16];
    float2 rsum = make_float2(0.f, 0.f);

    // ---- QK^T + bias + exp (fully unrolled => p in registers) ----
    #pragma unroll
    for (int kt = 0; kt < 16; kt++) {
        int colb = kt * 128 + w * 8 + g;
        float4 acc = make_float4(0.f, 0.f, 0.f, 0.f);
        #pragma unroll
        for (int ks = 0; ks < 8; ks++) {
            float kv0 = KT[(size_t)(ks * 8 + t) * Ss + colb];
            float kv1 = KT[(size_t)(ks * 8 + t + 4) * Ss + colb];
            mma_tf32(acc, qa[ks], __float_as_uint(kv0), __float_as_uint(kv1));
        }
        int gk = kt * 128 + w * 8 + 2 * t;
        float2 b0 = *(const float2*)&g_bias[(size_t)(q0 + g) * Ss + gk];
        float2 b1 = *(const float2*)&g_bias[(size_t)(q0 + g + 8) * Ss + gk];
        float4 pv;
        pv.x = fast_exp(fmaf(acc.x, scale, b0.x));
        pv.y = fast_exp(fmaf(acc.y, scale, b0.y));
        pv.z = fast_exp(fmaf(acc.z, scale, b1.x));
        pv.w = fast_exp(fmaf(acc.w, scale, b1.y));
        p[kt] = pv;
        rsum.x += pv.x + pv.y;
        rsum.y += pv.z + pv.w;
    }

    // ---- row-sum reduction ----
    rsum.x += __shfl_xor_sync(FULLM, rsum.x, 1);
    rsum.x += __shfl_xor_sync(FULLM, rsum.x, 2);
    rsum.y += __shfl_xor_sync(FULLM, rsum.y, 1);
    rsum.y += __shfl_xor_sync(FULLM, rsum.y, 2);
    if (t == 0) {
        sred[w * 18 + g] = rsum.x;
        sred[w * 18 + 8 + g] = rsum.y;
    }
    __syncthreads();
    {
        float v = (lane < 16) ? sred[lane * 18 + w] : 0.f;
        #pragma unroll
        for (int o = 8; o; o >>= 1) v += __shfl_xor_sync(FULLM, v, o);
        if (lane == 0) sinv[w] = 1.f / v;
    }
    __syncthreads();
    float invx = sinv[g], invy = sinv[8 + g];

    // ---- normalize, write attn (exact), round P for mma ----
    #pragma unroll
    for (int kt = 0; kt < 16; kt++) {
        float4 pv = p[kt];
        pv.x *= invx; pv.y *= invx; pv.z *= invy; pv.w *= invy;
        int gk = kt * 128 + w * 8 + 2 * t;
        *(float2*)&attn_out[(size_t)g * Ss + gk] = make_float2(pv.x, pv.y);
        *(float2*)&attn_out[(size_t)(g + 8) * Ss + gk] = make_float2(pv.z, pv.w);
        pv.x = rnd_tf32(pv.x); pv.y = rnd_tf32(pv.y);
        pv.z = rnd_tf32(pv.z); pv.w = rnd_tf32(pv.w);
        p[kt] = pv;
    }

    // ---- PV: per-warp partial; fully unrolled => p stays in registers ----
    float4 oacc[8];
    #pragma unroll
    for (int j = 0; j < 8; j++) oacc[j] = make_float4(0.f, 0.f, 0.f, 0.f);

    #pragma unroll
    for (int kt = 0; kt < 16; kt++) {
        float4 pk = p[kt];
        int src  = (g << 2) + (t >> 1);
        int src2 = src + 2;
        float lo, hi;
        uint32_t A[4];
        lo = __shfl_sync(FULLM, pk.x, src);  hi = __shfl_sync(FULLM, pk.y, src);
        A[0] = __float_as_uint((t & 1) ? hi : lo);
        lo = __shfl_sync(FULLM, pk.z, src);  hi = __shfl_sync(FULLM, pk.w, src);
        A[1] = __float_as_uint((t & 1) ? hi : lo);
        lo = __shfl_sync(FULLM, pk.x, src2); hi = __shfl_sync(FULLM, pk.y, src2);
        A[2] = __float_as_uint((t & 1) ? hi : lo);
        lo = __shfl_sync(FULLM, pk.z, src2); hi = __shfl_sync(FULLM, pk.w, src2);
        A[3] = __float_as_uint((t & 1) ? hi : lo);

        const float* Vb = V + (size_t)(kt * 128 + w * 8) * DK;
        #pragma unroll
        for (int j = 0; j < 8; j++) {
            float v0 = Vb[t * DK + j * 8 + g];
            float v1 = Vb[(t + 4) * DK + j * 8 + g];
            mma_tf32(oacc[j], A, __float_as_uint(v0), __float_as_uint(v1));
        }
    }

    // ---- reduction tree across 16 warps ----
    #pragma unroll
    for (int step = 8; step >= 1; step >>= 1) {
        __syncthreads();
        if (w >= step && w < 2 * step) {
            float* dst = &sacc[(w - step) * 1024 + lane * 4];
            #pragma unroll
            for (int j = 0; j < 8; j++) *(float4*)&dst[j * 128] = oacc[j];
        }
        __syncthreads();
        if (w < step) {
            const float* srcp = &sacc[w * 1024 + lane * 4];
            #pragma unroll
            for (int j = 0; j < 8; j++) {
                float4 o2 = *(const float4*)&srcp[j * 128];
                oacc[j].x += o2.x; oacc[j].y += o2.y;
                oacc[j].z += o2.z; oacc[j].w += o2.w;
            }
        }
    }

    if (w == 0) {
        #pragma unroll
        for (int j = 0; j < 8; j++) {
            int col = h * DK + j * 8 + 2 * t;
            float2 r0, r1;
            r0.x = rnd_tf32(oacc[j].x); r0.y = rnd_tf32(oacc[j].y);
            r1.x = rnd_tf32(oacc[j].z); r1.y = rnd_tf32(oacc[j].w);
            *(float2*)&g_x[((size_t)(b * Ss + q0 + g)) * Dd + col] = r0;
            *(float2*)&g_x[((size_t)(b * Ss + q0 + g + 8)) * Dd + col] = r1;
        }
    }
}

// ---------------- launch ----------------
extern "C" void kernel_launch(void* const* d_in, const int* in_sizes, int n_in,
                              void* d_out, int out_size) {
    const float* q    = (const float*)d_in[0];
    const float* k    = (const float*)d_in[1];
    const float* v    = (const float*)d_in[2];
    const int*   mask = (const int*)  d_in[3];
    const float* pos  = (const float*)d_in[4];
    const float* ln_g = (const float*)d_in[5];
    const float* ln_b = (const float*)d_in[6];
    const float* wq   = (const float*)d_in[7];
    const float* bq   = (const float*)d_in[8];
    const float* wk   = (const float*)d_in[9];
    const float* bk   = (const float*)d_in[10];
    const float* wv   = (const float*)d_in[11];
    const float* bv   = (const float*)d_in[12];
    const float* wo   = (const float*)d_in[13];
    const float* bo   = (const float*)d_in[14];
    const float* ls   = (const float*)d_in[15];
    float* out = (float*)d_out;

    bias_kernel<<<(Ss * (size_t)Ss) / 4096, 1024>>>(pos, mask);
    ln_kernel<<<dim3(BS, 3), 256>>>(q, k, v, ln_g, ln_b);
    wt_kernel<<<dim3(16, 16, 4), 256>>>(wq, wk, wv, wo);
    proj_qkv_kernel<<<dim3(BS / 64, Dd / 64, 3), 256>>>(bq, bk, bv);
    attn_kernel<<<dim3(Ss / TQ, Hh, Bb), 512>>>(out);
    proj_out_kernel<<<dim3(BS / 64, Dd / 64), 256>>>(bo, ls, out);
}

// round 10
// speedup vs baseline: 5.2105x; 1.2732x over previous
#include <cuda_runtime.h>
#include <math.h>
#include <stdint.h>

#define Bb 4
#define Ss 2048
#define Dd 512
#define Hh 8
#define DK 64
#define BS (Bb*Ss)          // 8192 rows
#define LN_EPS 1e-5f
#define NEG_BIG (-1e30f)

// ---------------- scratch (static device globals; no allocation) ----------------
__device__ float g_xn[3][(size_t)BS*Dd];                 // normalized q,k,v (tf32-rounded)
__device__ float g_qkvh[3][(size_t)Bb*Hh*Ss*DK];         // head-major Q,K,V (tf32-rounded)
__device__ float g_x[(size_t)BS*Dd];                     // attention output (tf32-rounded)
__device__ float g_wt[4][(size_t)Dd*Dd];                 // W^T, tf32-rounded: [n][k]
__device__ float g_bias2[(size_t)Ss*Ss];                 // bias in mma-fragment order (16.8 MB)

// ---------------- helpers ----------------
__device__ __forceinline__ uint32_t f2tf32(float x) {
    uint32_t r;
    asm volatile("cvt.rna.tf32.f32 %0, %1;" : "=r"(r) : "f"(x));
    return r;
}
__device__ __forceinline__ float rnd_tf32(float x) { return __uint_as_float(f2tf32(x)); }

__device__ __forceinline__ void mma_tf32(float4& d, const uint32_t a[4],
                                         uint32_t b0, uint32_t b1) {
    asm volatile(
        "mma.sync.aligned.m16n8k8.row.col.f32.tf32.tf32.f32 "
        "{%0,%1,%2,%3}, {%4,%5,%6,%7}, {%8,%9}, {%0,%1,%2,%3};\n"
        : "+f"(d.x), "+f"(d.y), "+f"(d.z), "+f"(d.w)
        : "r"(a[0]), "r"(a[1]), "r"(a[2]), "r"(a[3]), "r"(b0), "r"(b1));
}

__device__ __forceinline__ void cpa16(float* s, const float* g) {
    uint32_t sa = (uint32_t)__cvta_generic_to_shared(s);
    asm volatile("cp.async.ca.shared.global [%0], [%1], 16;\n" :: "r"(sa), "l"(g));
}
#define CP_COMMIT() asm volatile("cp.async.commit_group;\n")
template<int N> __device__ __forceinline__ void cp_wait() {
    asm volatile("cp.async.wait_group %0;\n" :: "n"(N));
}

// ---------------- Kernel 0: pack mask+pos into mma-fragment-ordered bias ----------------
// float4 id: ((qt*16 + kt)*16 + w)*8*32 + j*32 + lane holds
//   rows q = qt*128 + (w>>1)*16 + (lane>>2) (+8), cols c = kt*128 + (w&1)*64 + j*8 + 2*(lane&3) (+1)
// Total float4 = Ss*Ss/4 = 1,048,576 => grid 1024 x 1024 threads.
__global__ void __launch_bounds__(1024) bias2_kernel(
    const float* __restrict__ pos, const int* __restrict__ mask) {
    int idx = blockIdx.x * 1024 + threadIdx.x;      // 0 .. 1,048,575
    int lane = idx & 31;
    int j    = (idx >> 5) & 7;
    int w    = (idx >> 8) & 15;
    int kt   = (idx >> 12) & 15;
    int qt   = idx >> 16;                            // 0..15
    int g = lane >> 2, t = lane & 3;
    int wq = w >> 1, wk2 = w & 1;
    int q = qt * 128 + wq * 16 + g;
    int c = kt * 128 + wk2 * 64 + j * 8 + 2 * t;
    const float* p0 = &pos[q * Ss + c];
    const float* p1 = &pos[(q + 8) * Ss + c];
    const int*   m0 = &mask[q * Ss + c];
    const int*   m1 = &mask[(q + 8) * Ss + c];
    float4 o;
    o.x = m0[0] ? p0[0] : NEG_BIG;
    o.y = m0[1] ? p0[1] : NEG_BIG;
    o.z = m1[0] ? p1[0] : NEG_BIG;
    o.w = m1[1] ? p1[1] : NEG_BIG;
    ((float4*)g_bias2)[idx] = o;
}

// ---------------- Kernel 1: LayerNorm (tf32-rounded output) ----------------
__global__ void ln_kernel(const float* __restrict__ q, const float* __restrict__ k,
                          const float* __restrict__ v, const float* __restrict__ g,
                          const float* __restrict__ b) {
    int row = blockIdx.x;
    int which = blockIdx.y;
    const float* xs = which == 0 ? q : (which == 1 ? k : v);
    const float* x = xs + (size_t)row * Dd;
    float* y = g_xn[which] + (size_t)row * Dd;
    int t = threadIdx.x;

    float v0 = x[t], v1 = x[t + 256];
    float s = v0 + v1, s2 = v0 * v0 + v1 * v1;

    __shared__ float rs[8], rs2[8];
    #pragma unroll
    for (int o = 16; o; o >>= 1) {
        s  += __shfl_xor_sync(0xFFFFFFFFu, s,  o);
        s2 += __shfl_xor_sync(0xFFFFFFFFu, s2, o);
    }
    if ((t & 31) == 0) { rs[t >> 5] = s; rs2[t >> 5] = s2; }
    __syncthreads();
    __shared__ float smu, sinv;
    if (t == 0) {
        float S = 0.f, S2 = 0.f;
        #pragma unroll
        for (int i = 0; i < 8; i++) { S += rs[i]; S2 += rs2[i]; }
        float mu = S * (1.f / 512.f);
        float var = S2 * (1.f / 512.f) - mu * mu;
        smu = mu; sinv = rsqrtf(var + LN_EPS);
    }
    __syncthreads();
    float mu = smu, inv = sinv;
    y[t]       = rnd_tf32((v0 - mu) * inv * g[t]       + b[t]);
    y[t + 256] = rnd_tf32((v1 - mu) * inv * g[t + 256] + b[t + 256]);
}

// ---------------- Kernel 1b: weight transpose + tf32 round ----------------
__global__ void wt_kernel(const float* __restrict__ wq, const float* __restrict__ wk,
                          const float* __restrict__ wv, const float* __restrict__ wo) {
    __shared__ float tile[32][33];
    int z = blockIdx.z;
    const float* W = z == 0 ? wq : (z == 1 ? wk : (z == 2 ? wv : wo));
    int k0 = blockIdx.x * 32, n0 = blockIdx.y * 32;
    int c = threadIdx.x & 31, r0 = threadIdx.x >> 5;
    #pragma unroll
    for (int i = 0; i < 4; i++) {
        int r = r0 + i * 8;
        tile[r][c] = W[(size_t)(k0 + r) * Dd + n0 + c];
    }
    __syncthreads();
    #pragma unroll
    for (int i = 0; i < 4; i++) {
        int r = r0 + i * 8;
        g_wt[z][(size_t)(n0 + r) * Dd + k0 + c] = rnd_tf32(tile[c][r]);
    }
}

// ---------------- tf32 GEMM tile core (BM=64, BN=64, BK=32, cp.async 2-stage) ----------------
#define GSTG 2304   // one stage: 64 rows * 36

__device__ __forceinline__ void gemm_load_stage(
    const float* __restrict__ A, const float* __restrict__ Bt,
    int m0, int n0, int k0, float* sA, float* sB) {
    int tid = threadIdx.x;
    #pragma unroll
    for (int i = 0; i < 2; i++) {
        int idx = tid + i * 256;
        int m = idx >> 3, c = idx & 7;
        cpa16(&sA[m * 36 + c * 4], &A[(size_t)(m0 + m) * Dd + k0 + c * 4]);
    }
    #pragma unroll
    for (int i = 0; i < 2; i++) {
        int idx = tid + i * 256;
        int n = idx >> 3, c = idx & 7;
        cpa16(&sB[n * 36 + c * 4], &Bt[(size_t)(n0 + n) * Dd + k0 + c * 4]);
    }
}

__device__ __forceinline__ void gemm_tile_tf32(
    const float* __restrict__ A, const float* __restrict__ Bt,
    int m0, int n0, float4 acc[2][2], float* sA, float* sB) {
    int tid = threadIdx.x;
    int lane = tid & 31, w = tid >> 5;
    int g = lane >> 2, t = lane & 3;
    int wm = w >> 2, wn = w & 3;
    #pragma unroll
    for (int i = 0; i < 2; i++)
        #pragma unroll
        for (int j = 0; j < 2; j++) acc[i][j] = make_float4(0.f, 0.f, 0.f, 0.f);

    gemm_load_stage(A, Bt, m0, n0, 0, sA, sB);
    CP_COMMIT();

    for (int it = 0; it < 16; it++) {
        if (it < 15) {
            int s = (it + 1) & 1;
            gemm_load_stage(A, Bt, m0, n0, (it + 1) * 32, sA + s * GSTG, sB + s * GSTG);
            CP_COMMIT();
            cp_wait<1>();
        } else {
            cp_wait<0>();
        }
        __syncthreads();

        const float* cA = sA + (it & 1) * GSTG;
        const float* cB = sB + (it & 1) * GSTG;
        #pragma unroll
        for (int ks = 0; ks < 4; ks++) {
            int kk = ks * 8;
            uint32_t a[2][4];
            #pragma unroll
            for (int mi = 0; mi < 2; mi++) {
                const float* ap = &cA[(wm * 32 + mi * 16 + g) * 36 + kk + t];
                a[mi][0] = __float_as_uint(ap[0]);
                a[mi][1] = __float_as_uint(ap[8 * 36]);
                a[mi][2] = __float_as_uint(ap[4]);
                a[mi][3] = __float_as_uint(ap[8 * 36 + 4]);
            }
            #pragma unroll
            for (int nj = 0; nj < 2; nj++) {
                const float* bp = &cB[(wn * 16 + nj * 8 + g) * 36 + kk];
                uint32_t b0 = __float_as_uint(bp[t]);
                uint32_t b1 = __float_as_uint(bp[t + 4]);
                mma_tf32(acc[0][nj], a[0], b0, b1);
                mma_tf32(acc[1][nj], a[1], b0, b1);
            }
        }
        __syncthreads();
    }
}

// ---------------- Kernel 2: QKV projection (head-major epilogue) ----------------
__global__ void __launch_bounds__(256) proj_qkv_kernel(
    const float* __restrict__ bq, const float* __restrict__ bk, const float* __restrict__ bv) {
    __shared__ float sA[2 * GSTG];
    __shared__ float sB[2 * GSTG];
    int z = blockIdx.z;
    const float* bias = z == 0 ? bq : (z == 1 ? bk : bv);
    float* out = g_qkvh[z];
    int m0 = blockIdx.x * 64, n0 = blockIdx.y * 64;

    float4 acc[2][2];
    gemm_tile_tf32(g_xn[z], g_wt[z], m0, n0, acc, sA, sB);

    int lane = threadIdx.x & 31, w = threadIdx.x >> 5;
    int g = lane >> 2, t = lane & 3;
    int wm = w >> 2, wn = w & 3;
    #pragma unroll
    for (int mi = 0; mi < 2; mi++) {
        #pragma unroll
        for (int nj = 0; nj < 2; nj++) {
            int n = n0 + wn * 16 + nj * 8 + 2 * t;
            int hh = n >> 6, dd = n & 63;
            float b0 = bias[n], b1 = bias[n + 1];
            #pragma unroll
            for (int r = 0; r < 2; r++) {
                int m = m0 + wm * 32 + mi * 16 + g + r * 8;
                int bidx = m >> 11, srow = m & 2047;
                float2 val;
                if (r == 0) { val.x = acc[mi][nj].x + b0; val.y = acc[mi][nj].y + b1; }
                else        { val.x = acc[mi][nj].z + b0; val.y = acc[mi][nj].w + b1; }
                val.x = rnd_tf32(val.x); val.y = rnd_tf32(val.y);
                *(float2*)&out[(((size_t)(bidx * Hh + hh) * Ss + srow) * DK) + dd] = val;
            }
        }
    }
}

// ---------------- Kernel 4: output projection ----------------
__global__ void __launch_bounds__(256) proj_out_kernel(
    const float* __restrict__ bo, const float* __restrict__ ls, float* __restrict__ Cout) {
    __shared__ float sA[2 * GSTG];
    __shared__ float sB[2 * GSTG];
    int m0 = blockIdx.x * 64, n0 = blockIdx.y * 64;

    float4 acc[2][2];
    gemm_tile_tf32(g_x, g_wt[3], m0, n0, acc, sA, sB);

    int lane = threadIdx.x & 31, w = threadIdx.x >> 5;
    int g = lane >> 2, t = lane & 3;
    int wm = w >> 2, wn = w & 3;
    #pragma unroll
    for (int mi = 0; mi < 2; mi++) {
        #pragma unroll
        for (int nj = 0; nj < 2; nj++) {
            int n = n0 + wn * 16 + nj * 8 + 2 * t;
            float b0 = bo[n], b1 = bo[n + 1];
            float l0 = ls[n], l1 = ls[n + 1];
            #pragma unroll
            for (int r = 0; r < 2; r++) {
                int m = m0 + wm * 32 + mi * 16 + g + r * 8;
                float2 val;
                if (r == 0) { val.x = (acc[mi][nj].x + b0) * l0; val.y = (acc[mi][nj].y + b1) * l1; }
                else        { val.x = (acc[mi][nj].z + b0) * l0; val.y = (acc[mi][nj].w + b1) * l1; }
                *(float2*)&Cout[(size_t)m * Dd + n] = val;
            }
        }
    }
}

// ---------------- Kernel 3: attention — TQ=128, two-pass, smem-staged K/V ----------------
// 512 thr = 16 warps: warp w = (wq = w>>1 : 16 q-rows) x (wk2 = w&1 : 64-key half).
// Pass 1: QK^T + bias + exp, accumulate row sums (no P storage).
// Pass 2: recompute, normalize, write attn, PV-mma into O.
#define KSTRIDE 68
#define VSTRIDE 72
#define SK_ELEMS (128 * KSTRIDE)     // 8704
#define SV_ELEMS (128 * VSTRIDE)     // 9216
#define ATTN_SMEM_BYTES ((2 * SK_ELEMS + 2 * SV_ELEMS) * 4)   // 143,360
#define FULLM 0xFFFFFFFFu

__device__ __forceinline__ void stage_k(const float* __restrict__ K, int kt, float* dst) {
    int tid = threadIdx.x;
    #pragma unroll
    for (int i = 0; i < 4; i++) {
        int idx = tid + i * 512;
        int key = idx >> 4, d4 = idx & 15;
        cpa16(&dst[key * KSTRIDE + d4 * 4], &K[(size_t)(kt * 128 + key) * DK + d4 * 4]);
    }
}
__device__ __forceinline__ void stage_v(const float* __restrict__ V, int kt, float* dst) {
    int tid = threadIdx.x;
    #pragma unroll
    for (int i = 0; i < 4; i++) {
        int idx = tid + i * 512;
        int key = idx >> 4, d4 = idx & 15;
        cpa16(&dst[key * VSTRIDE + d4 * 4], &V[(size_t)(kt * 128 + key) * DK + d4 * 4]);
    }
}

__global__ void __launch_bounds__(512, 1) attn_kernel(float* __restrict__ d_out) {
    extern __shared__ float smem[];
    float* sK0 = smem;
    float* sK1 = smem + SK_ELEMS;
    float* sV0 = smem + 2 * SK_ELEMS;
    float* sV1 = sV0 + SV_ELEMS;
    __shared__ float sred[16][16];
    __shared__ float sinvs[128];

    int qb = blockIdx.x, h = blockIdx.y, b = blockIdx.z;
    const float* Q = g_qkvh[0] + (size_t)(b * Hh + h) * Ss * DK;
    const float* K = g_qkvh[1] + (size_t)(b * Hh + h) * Ss * DK;
    const float* V = g_qkvh[2] + (size_t)(b * Hh + h) * Ss * DK;
    int q0 = qb * 128;

    int tid = threadIdx.x;
    int lane = tid & 31, w = tid >> 5;
    int g = lane >> 2, t = lane & 3;
    int wq = w >> 1, wk2 = w & 1;
    const float scale = 0.125f;

    // Q fragments for rows q0 + wq*16 + {g, g+8}
    uint32_t qa[8][4];
    {
        const float* Qb = Q + (size_t)(q0 + wq * 16) * DK;
        #pragma unroll
        for (int ks = 0; ks < 8; ks++) {
            int c = ks * 8 + t;
            qa[ks][0] = __float_as_uint(Qb[g * DK + c]);
            qa[ks][1] = __float_as_uint(Qb[(g + 8) * DK + c]);
            qa[ks][2] = __float_as_uint(Qb[g * DK + c + 4]);
            qa[ks][3] = __float_as_uint(Qb[(g + 8) * DK + c + 4]);
        }
    }

    // fragment-ordered bias base: ((qb*16 + kt)*16 + w)*256 + j*32 + lane
    const float4* b2 = (const float4*)g_bias2 + ((size_t)(qb * 16) * 16 + w) * 256 + lane;

    // ================= PASS 1: row sums =================
    float2 rsum = make_float2(0.f, 0.f);
    stage_k(K, 0, sK0);
    CP_COMMIT();

    for (int kt = 0; kt < 16; kt++) {
        if (kt < 15) {
            __syncthreads();
            stage_k(K, kt + 1, (kt & 1) ? sK0 : sK1);
            CP_COMMIT();
            cp_wait<1>();
        } else {
            cp_wait<0>();
        }
        __syncthreads();

        const float* cK = (kt & 1) ? sK1 : sK0;
        const float* kbase = &cK[(wk2 * 64 + g) * KSTRIDE + t];
        #pragma unroll
        for (int j = 0; j < 8; j++) {
            float4 acc = make_float4(0.f, 0.f, 0.f, 0.f);
            const float* kp = kbase + j * 8 * KSTRIDE;
            #pragma unroll
            for (int ks = 0; ks < 8; ks++) {
                mma_tf32(acc, qa[ks], __float_as_uint(kp[ks * 8]),
                                      __float_as_uint(kp[ks * 8 + 4]));
            }
            float4 bf = b2[kt * 4096 + j * 32];
            float e0 = __expf(fmaf(acc.x, scale, bf.x));
            float e1 = __expf(fmaf(acc.y, scale, bf.y));
            float e2 = __expf(fmaf(acc.z, scale, bf.z));
            float e3 = __expf(fmaf(acc.w, scale, bf.w));
            rsum.x += e0 + e1;
            rsum.y += e2 + e3;
        }
    }

    // reduce row sums: over t lanes, then over wk2 halves
    rsum.x += __shfl_xor_sync(FULLM, rsum.x, 1);
    rsum.x += __shfl_xor_sync(FULLM, rsum.x, 2);
    rsum.y += __shfl_xor_sync(FULLM, rsum.y, 1);
    rsum.y += __shfl_xor_sync(FULLM, rsum.y, 2);
    if (t == 0) {
        sred[w][g] = rsum.x;
        sred[w][g + 8] = rsum.y;
    }
    __syncthreads();
    if (tid < 128) {
        int wqr = tid >> 4, rr = tid & 15;
        sinvs[tid] = 1.f / (sred[wqr * 2][rr] + sred[wqr * 2 + 1][rr]);
    }
    __syncthreads();
    float invx = sinvs[wq * 16 + g];
    float invy = sinvs[wq * 16 + g + 8];

    // ================= PASS 2: attn write + PV =================
    float* attnp = d_out + (size_t)BS * Dd
                 + ((size_t)((b * Hh + h) * Ss) + q0 + wq * 16) * Ss;

    float4 oacc[8];
    #pragma unroll
    for (int j = 0; j < 8; j++) oacc[j] = make_float4(0.f, 0.f, 0.f, 0.f);

    stage_k(K, 0, sK0);
    stage_v(V, 0, sV0);
    CP_COMMIT();

    for (int kt = 0; kt < 16; kt++) {
        if (kt < 15) {
            __syncthreads();
            stage_k(K, kt + 1, (kt & 1) ? sK0 : sK1);
            stage_v(V, kt + 1, (kt & 1) ? sV0 : sV1);
            CP_COMMIT();
            cp_wait<1>();
        } else {
            cp_wait<0>();
        }
        __syncthreads();

        const float* cK = (kt & 1) ? sK1 : sK0;
        const float* cV = (kt & 1) ? sV1 : sV0;
        const float* kbase = &cK[(wk2 * 64 + g) * KSTRIDE + t];
        const float* vbase = &cV[(wk2 * 64 + t) * VSTRIDE + g];

        #pragma unroll
        for (int j = 0; j < 8; j++) {
            float4 acc = make_float4(0.f, 0.f, 0.f, 0.f);
            const float* kp = kbase + j * 8 * KSTRIDE;
            #pragma unroll
            for (int ks = 0; ks < 8; ks++) {
                mma_tf32(acc, qa[ks], __float_as_uint(kp[ks * 8]),
                                      __float_as_uint(kp[ks * 8 + 4]));
            }
            float4 bf = b2[kt * 4096 + j * 32];
            float4 pv;
            pv.x = __expf(fmaf(acc.x, scale, bf.x)) * invx;
            pv.y = __expf(fmaf(acc.y, scale, bf.y)) * invx;
            pv.z = __expf(fmaf(acc.z, scale, bf.z)) * invy;
            pv.w = __expf(fmaf(acc.w, scale, bf.w)) * invy;

            int gc = kt * 128 + wk2 * 64 + j * 8 + 2 * t;
            *(float2*)&attnp[(size_t)g * Ss + gc] = make_float2(pv.x, pv.y);
            *(float2*)&attnp[(size_t)(g + 8) * Ss + gc] = make_float2(pv.z, pv.w);

            pv.x = rnd_tf32(pv.x); pv.y = rnd_tf32(pv.y);
            pv.z = rnd_tf32(pv.z); pv.w = rnd_tf32(pv.w);

            // permute S fragment -> PV A fragment (within-warp shuffles)
            int src  = (g << 2) + (t >> 1);
            int src2 = src + 2;
            float lo, hi;
            uint32_t A[4];
            lo = __shfl_sync(FULLM, pv.x, src);  hi = __shfl_sync(FULLM, pv.y, src);
            A[0] = __float_as_uint((t & 1) ? hi : lo);
            lo = __shfl_sync(FULLM, pv.z, src);  hi = __shfl_sync(FULLM, pv.w, src);
            A[1] = __float_as_uint((t & 1) ? hi : lo);
            lo = __shfl_sync(FULLM, pv.x, src2); hi = __shfl_sync(FULLM, pv.y, src2);
            A[2] = __float_as_uint((t & 1) ? hi : lo);
            lo = __shfl_sync(FULLM, pv.z, src2); hi = __shfl_sync(FULLM, pv.w, src2);
            A[3] = __float_as_uint((t & 1) ? hi : lo);

            const float* vp = vbase + j * 8 * VSTRIDE;
            #pragma unroll
            for (int jj = 0; jj < 8; jj++) {
                float v0 = vp[jj * 8];
                float v1 = vp[4 * VSTRIDE + jj * 8];
                mma_tf32(oacc[jj], A, __float_as_uint(v0), __float_as_uint(v1));
            }
        }
    }

    // ---- combine wk2 halves via smem (alias staging buffers), write g_x ----
    __syncthreads();
    float* sacc = smem;   // 8 wq * 8 jj * 128 floats = 8192 floats
    if (wk2 == 1) {
        float* dst = &sacc[(wq * 8) * 128 + lane * 4];
        #pragma unroll
        for (int jj = 0; jj < 8; jj++) *(float4*)&dst[jj * 128] = oacc[jj];
    }
    __syncthreads();
    if (wk2 == 0) {
        const float* srcp = &sacc[(wq * 8) * 128 + lane * 4];
        #pragma unroll
        for (int jj = 0; jj < 8; jj++) {
            float4 o2 = *(const float4*)&srcp[jj * 128];
            float4 o = oacc[jj];
            o.x += o2.x; o.y += o2.y; o.z += o2.z; o.w += o2.w;
            int row0 = b * Ss + q0 + wq * 16 + g;
            int col = h * DK + jj * 8 + 2 * t;
            float2 r0, r1;
            r0.x = rnd_tf32(o.x); r0.y = rnd_tf32(o.y);
            r1.x = rnd_tf32(o.z); r1.y = rnd_tf32(o.w);
            *(float2*)&g_x[(size_t)row0 * Dd + col] = r0;
            *(float2*)&g_x[(size_t)(row0 + 8) * Dd + col] = r1;
        }
    }
}

// ---------------- launch ----------------
extern "C" void kernel_launch(void* const* d_in, const int* in_sizes, int n_in,
                              void* d_out, int out_size) {
    const float* q    = (const float*)d_in[0];
    const float* k    = (const float*)d_in[1];
    const float* v    = (const float*)d_in[2];
    const int*   mask = (const int*)  d_in[3];
    const float* pos  = (const float*)d_in[4];
    const float* ln_g = (const float*)d_in[5];
    const float* ln_b = (const float*)d_in[6];
    const float* wq   = (const float*)d_in[7];
    const float* bq   = (const float*)d_in[8];
    const float* wk   = (const float*)d_in[9];
    const float* bk   = (const float*)d_in[10];
    const float* wv   = (const float*)d_in[11];
    const float* bv   = (const float*)d_in[12];
    const float* wo   = (const float*)d_in[13];
    const float* bo   = (const float*)d_in[14];
    const float* ls   = (const float*)d_in[15];
    float* out = (float*)d_out;

    cudaFuncSetAttribute(attn_kernel, cudaFuncAttributeMaxDynamicSharedMemorySize,
                         ATTN_SMEM_BYTES);

    bias2_kernel<<<1024, 1024>>>(pos, mask);
    ln_kernel<<<dim3(BS, 3), 256>>>(q, k, v, ln_g, ln_b);
    wt_kernel<<<dim3(16, 16, 4), 256>>>(wq, wk, wv, wo);
    proj_qkv_kernel<<<dim3(BS / 64, Dd / 64, 3), 256>>>(bq, bk, bv);
    attn_kernel<<<dim3(Ss / 128, Hh, Bb), 512, ATTN_SMEM_BYTES>>>(out);
    proj_out_kernel<<<dim3(BS / 64, Dd / 64), 256>>>(bo, ls, out);
}